// round 9
// baseline (speedup 1.0000x reference)
#include <cuda_runtime.h>
#include <cuda_bf16.h>
#include <math.h>
#include <stdint.h>

// ---------------- problem constants ----------------
#define BB 4
#define NN 4096
#define DD 1024
#define HH 16
#define HD 64
#define MLP 4096
#define MM (BB*NN)          // 16384 rows
#define K3D (3*DD)          // 3072
#define K3M (3*MLP)         // 12288

// ---------------- scratch (device globals; no allocation allowed) ------
// packed bf16 activations: A' = [hi | lo | hi] along K
__device__ __align__(256) __nv_bfloat16 g_xnp[(size_t)MM * K3D];
__device__ __align__(256) __nv_bfloat16 g_ap [(size_t)MM * K3D];
__device__ __align__(256) __nv_bfloat16 g_hp [(size_t)MM * K3M];
__device__ __align__(256) float g_q[(size_t)MM * DD];
__device__ __align__(256) float g_k[(size_t)MM * DD];
__device__ __align__(256) float g_v[(size_t)MM * DD];
__device__ __align__(256) float g_x[(size_t)MM * DD];
// packed transposed weights: B' = [hi | hi | lo] along K,  [N][3K]
__device__ __align__(256) __nv_bfloat16 g_wqp[(size_t)DD * K3D];
__device__ __align__(256) __nv_bfloat16 g_wkp[(size_t)DD * K3D];
__device__ __align__(256) __nv_bfloat16 g_wvp[(size_t)DD * K3D];
__device__ __align__(256) __nv_bfloat16 g_wop[(size_t)DD * K3D];
__device__ __align__(256) __nv_bfloat16 g_fcp[(size_t)MLP * K3D];
__device__ __align__(256) __nv_bfloat16 g_pjp[(size_t)DD * K3M];

// ================= PTX helpers (compute_103-safe: sm_80+ features) =====
__device__ __forceinline__ uint32_t smem_u32(const void* p) {
    uint32_t a;
    asm("{ .reg .u64 t; cvta.to.shared.u64 t, %1; cvt.u32.u64 %0, t; }" : "=r"(a) : "l"(p));
    return a;
}
__device__ __forceinline__ void cp16(uint32_t sdst, const void* gsrc) {
    asm volatile("cp.async.cg.shared.global [%0], [%1], 16;" :: "r"(sdst), "l"(gsrc) : "memory");
}
__device__ __forceinline__ void ldm4(uint32_t* r, uint32_t a) {
    asm volatile("ldmatrix.sync.aligned.m8n8.x4.shared.b16 {%0,%1,%2,%3}, [%4];"
        : "=r"(r[0]), "=r"(r[1]), "=r"(r[2]), "=r"(r[3]) : "r"(a));
}
__device__ __forceinline__ void mma16816(float* d, const uint32_t* a, const uint32_t* b) {
    asm volatile("mma.sync.aligned.m16n8k16.row.col.f32.bf16.bf16.f32 "
        "{%0,%1,%2,%3},{%4,%5,%6,%7},{%8,%9},{%0,%1,%2,%3};"
        : "+f"(d[0]), "+f"(d[1]), "+f"(d[2]), "+f"(d[3])
        : "r"(a[0]), "r"(a[1]), "r"(a[2]), "r"(a[3]), "r"(b[0]), "r"(b[1]));
}

// ================= HMMA GEMM: C[M,N] = A[M,Keff] @ B[N,Keff]^T =========
// CTA tile 128x256, 8 warps (2m x 4n) of 64x64, BKC=64, 3 stages.
// EPI: 0 = +bias (fp32), 1 = +bias+R (fp32), 2 = gelu(+bias) -> packed bf16
#define BM 128
#define BN 256
#define BKC 64
#define PITCHB 144                     // bytes per smem row (128B data + 16B pad)
#define A_SB (128 * PITCHB)            // 18432
#define B_SB (256 * PITCHB)            // 36864
#define STAGE_SB (A_SB + B_SB)         // 55296
#define NSTAGE 3
#define SMEM_BYTES (NSTAGE * STAGE_SB) // 165888

template<int EPI>
__global__ __launch_bounds__(256, 1) void mma_gemm(
    const __nv_bfloat16* __restrict__ A, const __nv_bfloat16* __restrict__ B,
    const float* __restrict__ bias, const float* __restrict__ Rres,
    float* __restrict__ Cf, __nv_bfloat16* __restrict__ Cp,
    int M, int N, int Keff)
{
    extern __shared__ char smem[];
    const uint32_t sb = smem_u32(smem);
    const int tid = threadIdx.x;
    const int bm = blockIdx.y * BM, bn = blockIdx.x * BN;
    const int w = tid >> 5, lane = tid & 31;
    const int wm = w & 1, wn = w >> 1;       // warp grid 2(m) x 4(n), 64x64 tiles

    float acc[4][8][4];
    #pragma unroll
    for (int i = 0; i < 4; i++)
        #pragma unroll
        for (int j = 0; j < 8; j++)
            #pragma unroll
            for (int t = 0; t < 4; t++) acc[i][j][t] = 0.f;

    const int KC = Keff / BKC;

    auto load_stage = [&](int st, int c) {
        const uint32_t s0 = sb + st * STAGE_SB;
        const int k0 = c * BKC;
        #pragma unroll
        for (int i = 0; i < 4; i++) {               // A: 1024 chunks
            const int idx = tid + i * 256;
            const int r = idx >> 3, ch = idx & 7;
            cp16(s0 + r * PITCHB + ch * 16,
                 A + (size_t)(bm + r) * Keff + k0 + ch * 8);
        }
        #pragma unroll
        for (int i = 0; i < 8; i++) {               // B: 2048 chunks
            const int idx = tid + i * 256;
            const int r = idx >> 3, ch = idx & 7;
            cp16(s0 + A_SB + r * PITCHB + ch * 16,
                 B + (size_t)(bn + r) * Keff + k0 + ch * 8);
        }
        asm volatile("cp.async.commit_group;" ::: "memory");
    };

    load_stage(0, 0);
    load_stage(1, 1);

    for (int c = 0; c < KC; c++) {
        const int st = c % NSTAGE;
        asm volatile("cp.async.wait_group 1;" ::: "memory");
        __syncthreads();

        if (c + 2 < KC) load_stage((c + 2) % NSTAGE, c + 2);
        else asm volatile("cp.async.commit_group;" ::: "memory");

        const uint32_t sA = sb + st * STAGE_SB;
        const uint32_t sB = sA + A_SB;

        #pragma unroll
        for (int ks = 0; ks < 4; ks++) {
            const int kc = ks * 16;
            uint32_t afr[4][4], bfr[8][2];
            #pragma unroll
            for (int mt = 0; mt < 4; mt++) {
                const int row = wm * 64 + mt * 16 + (lane & 15);
                const int col = kc + (lane >> 4) * 8;
                ldm4(afr[mt], sA + row * PITCHB + col * 2);
            }
            #pragma unroll
            for (int np = 0; np < 4; np++) {
                const int n = wn * 64 + np * 16 + ((lane >> 4) & 1) * 8 + (lane & 7);
                const int col = kc + ((lane >> 3) & 1) * 8;
                uint32_t r[4];
                ldm4(r, sB + n * PITCHB + col * 2);
                bfr[2 * np][0] = r[0]; bfr[2 * np][1] = r[1];
                bfr[2 * np + 1][0] = r[2]; bfr[2 * np + 1][1] = r[3];
            }
            #pragma unroll
            for (int mt = 0; mt < 4; mt++)
                #pragma unroll
                for (int nt = 0; nt < 8; nt++)
                    mma16816(acc[mt][nt], afr[mt], bfr[nt]);
        }
    }

    // -------- epilogue --------
    const int r0 = lane >> 2, cp2 = (lane & 3) * 2;
    #pragma unroll
    for (int mt = 0; mt < 4; mt++) {
        #pragma unroll
        for (int nt = 0; nt < 8; nt++) {
            const int col = bn + wn * 64 + nt * 8 + cp2;
            const float2 bv = *(const float2*)(bias + col);
            #pragma unroll
            for (int half = 0; half < 2; half++) {
                const int row = bm + wm * 64 + mt * 16 + r0 + half * 8;
                float v0 = acc[mt][nt][2 * half + 0] + bv.x;
                float v1 = acc[mt][nt][2 * half + 1] + bv.y;
                if (EPI == 1) {
                    const float2 rv = *(const float2*)(Rres + (size_t)row * N + col);
                    v0 += rv.x; v1 += rv.y;
                }
                if (EPI == 2) {
                    v0 = 0.5f * v0 * (1.0f + erff(v0 * 0.70710678118654752f));
                    v1 = 0.5f * v1 * (1.0f + erff(v1 * 0.70710678118654752f));
                    const __nv_bfloat16 h0 = __float2bfloat16(v0);
                    const __nv_bfloat16 h1 = __float2bfloat16(v1);
                    const __nv_bfloat16 l0 = __float2bfloat16(v0 - __bfloat162float(h0));
                    const __nv_bfloat16 l1 = __float2bfloat16(v1 - __bfloat162float(h1));
                    const size_t o = (size_t)row * (3 * (size_t)N) + col;
                    *(__nv_bfloat162*)(Cp + o)         = __nv_bfloat162(h0, h1);
                    *(__nv_bfloat162*)(Cp + o + N)     = __nv_bfloat162(l0, l1);
                    *(__nv_bfloat162*)(Cp + o + 2 * N) = __nv_bfloat162(h0, h1);
                } else {
                    *(float2*)(Cf + (size_t)row * N + col) = make_float2(v0, v1);
                }
            }
        }
    }
}

// ---------------- weight transpose + pack: W[K][N] -> T[N][3K] ---------
// T = [hi | hi | lo]
__global__ __launch_bounds__(256) void transpose_pack(
    const float* __restrict__ W, __nv_bfloat16* __restrict__ T, int K, int N)
{
    __shared__ float t[32][33];
    const int n0 = blockIdx.x * 32, k0 = blockIdx.y * 32;
    const int tx = threadIdx.x & 31, ty = threadIdx.x >> 5;  // 32 x 8
    #pragma unroll
    for (int i = 0; i < 32; i += 8)
        t[ty + i][tx] = W[(size_t)(k0 + ty + i) * N + n0 + tx];
    __syncthreads();
    #pragma unroll
    for (int i = 0; i < 32; i += 8) {
        const float v = t[tx][ty + i];
        const __nv_bfloat16 h = __float2bfloat16(v);
        const __nv_bfloat16 l = __float2bfloat16(v - __bfloat162float(h));
        const size_t o = (size_t)(n0 + ty + i) * (3 * (size_t)K) + k0 + tx;
        T[o]         = h;
        T[o + K]     = h;
        T[o + 2 * K] = l;
    }
}

// ---------------- LayerNorm -> packed bf16 [hi|lo|hi] ------------------
__global__ __launch_bounds__(256) void ln_pack_kernel(
    const float* __restrict__ X, const float* __restrict__ w,
    const float* __restrict__ b, __nv_bfloat16* __restrict__ Yp)
{
    const int row = blockIdx.x;
    const int tid = threadIdx.x;
    const float* x = X + (size_t)row * DD;

    float4 xv = *(const float4*)(x + tid * 4);
    float s  = xv.x + xv.y + xv.z + xv.w;
    float s2 = fmaf(xv.x, xv.x, fmaf(xv.y, xv.y, fmaf(xv.z, xv.z, xv.w * xv.w)));
    #pragma unroll
    for (int o = 16; o; o >>= 1) {
        s  += __shfl_xor_sync(0xFFFFFFFFu, s,  o);
        s2 += __shfl_xor_sync(0xFFFFFFFFu, s2, o);
    }
    __shared__ float sh[8], sh2[8];
    const int lane = tid & 31, wid = tid >> 5;
    if (lane == 0) { sh[wid] = s; sh2[wid] = s2; }
    __syncthreads();
    float S = 0.f, S2 = 0.f;
    #pragma unroll
    for (int i = 0; i < 8; i++) { S += sh[i]; S2 += sh2[i]; }
    const float mean = S * (1.0f / DD);
    const float var  = S2 * (1.0f / DD) - mean * mean;
    const float inv  = rsqrtf(var + 1e-5f);

    float4 wv = *(const float4*)(w + tid * 4);
    float4 bv = *(const float4*)(b + tid * 4);
    float y[4];
    y[0] = (xv.x - mean) * inv * wv.x + bv.x;
    y[1] = (xv.y - mean) * inv * wv.y + bv.y;
    y[2] = (xv.z - mean) * inv * wv.z + bv.z;
    y[3] = (xv.w - mean) * inv * wv.w + bv.w;

    __nv_bfloat16 h[4], l[4];
    #pragma unroll
    for (int t = 0; t < 4; t++) {
        h[t] = __float2bfloat16(y[t]);
        l[t] = __float2bfloat16(y[t] - __bfloat162float(h[t]));
    }
    const size_t o = (size_t)row * K3D + tid * 4;
    *(__nv_bfloat162*)(Yp + o)              = __nv_bfloat162(h[0], h[1]);
    *(__nv_bfloat162*)(Yp + o + 2)          = __nv_bfloat162(h[2], h[3]);
    *(__nv_bfloat162*)(Yp + o + DD)         = __nv_bfloat162(l[0], l[1]);
    *(__nv_bfloat162*)(Yp + o + DD + 2)     = __nv_bfloat162(l[2], l[3]);
    *(__nv_bfloat162*)(Yp + o + 2 * DD)     = __nv_bfloat162(h[0], h[1]);
    *(__nv_bfloat162*)(Yp + o + 2 * DD + 2) = __nv_bfloat162(h[2], h[3]);
}

// ---------------- fused per-token linear attention -> packed bf16 ------
__device__ __forceinline__ float elu1(float x) {
    return x > 0.f ? x + 1.0f : expf(x);
}

__global__ __launch_bounds__(256) void attn_kernel(
    const float* __restrict__ Q, const float* __restrict__ K_,
    const float* __restrict__ V, __nv_bfloat16* __restrict__ Op)
{
    __shared__ float fq[HH][HD];
    __shared__ float fk[HH][HD];
    __shared__ float vv[HH][HD];
    __shared__ float kv[HD][HD];
    __shared__ float ksum[HD];

    const size_t base  = (size_t)blockIdx.x * DD;
    const size_t base3 = (size_t)blockIdx.x * K3D;
    const int tid = threadIdx.x;

    {
        float4 q4 = *(const float4*)(Q  + base + tid * 4);
        float4 k4 = *(const float4*)(K_ + base + tid * 4);
        float4 v4 = *(const float4*)(V  + base + tid * 4);
        float* fqf = &fq[0][0]; float* fkf = &fk[0][0]; float* vvf = &vv[0][0];
        fqf[tid*4+0] = elu1(q4.x); fqf[tid*4+1] = elu1(q4.y);
        fqf[tid*4+2] = elu1(q4.z); fqf[tid*4+3] = elu1(q4.w);
        fkf[tid*4+0] = elu1(k4.x); fkf[tid*4+1] = elu1(k4.y);
        fkf[tid*4+2] = elu1(k4.z); fkf[tid*4+3] = elu1(k4.w);
        vvf[tid*4+0] = v4.x; vvf[tid*4+1] = v4.y;
        vvf[tid*4+2] = v4.z; vvf[tid*4+3] = v4.w;
    }
    __syncthreads();

    if (tid < HD) {
        float s = 0.f;
        #pragma unroll
        for (int h = 0; h < HH; h++) s += fk[h][tid];
        ksum[tid] = s;
    }
    {
        const int e = tid & 63;
        const int d0 = tid >> 6;
        #pragma unroll
        for (int j = 0; j < 16; j++) {
            const int d = d0 + j * 4;
            float s = 0.f;
            #pragma unroll
            for (int h = 0; h < HH; h++) s = fmaf(fk[h][d], vv[h][e], s);
            kv[d][e] = s;
        }
    }
    __syncthreads();
    {
        const int e = tid & 63;
        const int h0 = tid >> 6;
        #pragma unroll
        for (int j = 0; j < 4; j++) {
            const int h = h0 + j * 4;
            float s = 0.f, sq = 0.f;
            #pragma unroll
            for (int d = 0; d < HD; d++) {
                const float f = fq[h][d];
                s  = fmaf(f, kv[d][e], s);
                sq = fmaf(f, ksum[d], sq);
            }
            const float val = s / (sq + 1e-6f);
            const __nv_bfloat16 hi = __float2bfloat16(val);
            const __nv_bfloat16 lo = __float2bfloat16(val - __bfloat162float(hi));
            const size_t o = base3 + h * HD + e;
            Op[o]          = hi;
            Op[o + DD]     = lo;
            Op[o + 2 * DD] = hi;
        }
    }
}

// ---------------- launch ----------------
extern "C" void kernel_launch(void* const* d_in, const int* in_sizes, int n_in,
                              void* d_out, int out_size)
{
    const float* q_x    = (const float*)d_in[0];
    const float* ln1_w  = (const float*)d_in[1];
    const float* ln1_b  = (const float*)d_in[2];
    const float* wq     = (const float*)d_in[3];
    const float* bq     = (const float*)d_in[4];
    const float* wk     = (const float*)d_in[5];
    const float* bk     = (const float*)d_in[6];
    const float* wv     = (const float*)d_in[7];
    const float* bv     = (const float*)d_in[8];
    const float* wo     = (const float*)d_in[9];
    const float* bo     = (const float*)d_in[10];
    const float* ln2_w  = (const float*)d_in[11];
    const float* ln2_b  = (const float*)d_in[12];
    const float* fc_w   = (const float*)d_in[13];
    const float* fc_b   = (const float*)d_in[14];
    const float* proj_w = (const float*)d_in[15];
    const float* proj_b = (const float*)d_in[16];
    float* out = (float*)d_out;

    __nv_bfloat16 *xnp, *ap, *hp, *wqp, *wkp, *wvp, *wop, *fcp, *pjp;
    float *q, *k, *v, *x;
    cudaGetSymbolAddress((void**)&xnp, g_xnp);
    cudaGetSymbolAddress((void**)&ap,  g_ap);
    cudaGetSymbolAddress((void**)&hp,  g_hp);
    cudaGetSymbolAddress((void**)&q,   g_q);
    cudaGetSymbolAddress((void**)&k,   g_k);
    cudaGetSymbolAddress((void**)&v,   g_v);
    cudaGetSymbolAddress((void**)&x,   g_x);
    cudaGetSymbolAddress((void**)&wqp, g_wqp);
    cudaGetSymbolAddress((void**)&wkp, g_wkp);
    cudaGetSymbolAddress((void**)&wvp, g_wvp);
    cudaGetSymbolAddress((void**)&wop, g_wop);
    cudaGetSymbolAddress((void**)&fcp, g_fcp);
    cudaGetSymbolAddress((void**)&pjp, g_pjp);

    cudaFuncSetAttribute(mma_gemm<0>, cudaFuncAttributeMaxDynamicSharedMemorySize, SMEM_BYTES);
    cudaFuncSetAttribute(mma_gemm<1>, cudaFuncAttributeMaxDynamicSharedMemorySize, SMEM_BYTES);
    cudaFuncSetAttribute(mma_gemm<2>, cudaFuncAttributeMaxDynamicSharedMemorySize, SMEM_BYTES);

    // weight prep: transpose + bf16 hi/lo pack  [N][3K]
    transpose_pack<<<dim3(DD/32,  DD/32),  256>>>(wq,     wqp, DD,  DD);
    transpose_pack<<<dim3(DD/32,  DD/32),  256>>>(wk,     wkp, DD,  DD);
    transpose_pack<<<dim3(DD/32,  DD/32),  256>>>(wv,     wvp, DD,  DD);
    transpose_pack<<<dim3(DD/32,  DD/32),  256>>>(wo,     wop, DD,  DD);
    transpose_pack<<<dim3(MLP/32, DD/32),  256>>>(fc_w,   fcp, DD,  MLP);
    transpose_pack<<<dim3(DD/32,  MLP/32), 256>>>(proj_w, pjp, MLP, DD);

    const dim3 gD (DD  / BN, MM / BM);   // (4, 128)
    const dim3 gML(MLP / BN, MM / BM);   // (16, 128)

    // 1) xn = LN1(q_x) -> packed bf16
    ln_pack_kernel<<<MM, 256>>>(q_x, ln1_w, ln1_b, xnp);
    // 2) q/k/v = xn @ w* + b*  (fp32 out)
    mma_gemm<0><<<gD, 256, SMEM_BYTES>>>(xnp, wqp, bq, nullptr, q, nullptr, MM, DD, K3D);
    mma_gemm<0><<<gD, 256, SMEM_BYTES>>>(xnp, wkp, bk, nullptr, k, nullptr, MM, DD, K3D);
    mma_gemm<0><<<gD, 256, SMEM_BYTES>>>(xnp, wvp, bv, nullptr, v, nullptr, MM, DD, K3D);
    // 3) fused per-token linear attention -> packed bf16
    attn_kernel<<<MM, 256>>>(q, k, v, ap);
    // 4) x = q_x + attn @ wo + bo  (fp32 out)
    mma_gemm<1><<<gD, 256, SMEM_BYTES>>>(ap, wop, bo, q_x, x, nullptr, MM, DD, K3D);
    // 5) xn2 = LN2(x) -> packed bf16
    ln_pack_kernel<<<MM, 256>>>(x, ln2_w, ln2_b, xnp);
    // 6) h = gelu(xn2 @ fc_w + fc_b) -> packed bf16
    mma_gemm<2><<<gML, 256, SMEM_BYTES>>>(xnp, fcp, fc_b, nullptr, nullptr, hp, MM, MLP, K3D);
    // 7) out = x + h @ proj_w + proj_b  (fp32 out)
    mma_gemm<1><<<gD, 256, SMEM_BYTES>>>(hp, pjp, proj_b, x, out, nullptr, MM, DD, K3M);
}

// round 10
// speedup vs baseline: 1.0147x; 1.0147x over previous
#include <cuda_runtime.h>
#include <cuda_bf16.h>
#include <math.h>
#include <stdint.h>

// ---------------- problem constants ----------------
#define BB 4
#define NN 4096
#define DD 1024
#define HH 16
#define HD 64
#define MLP 4096
#define MM (BB*NN)          // 16384 rows
#define K3D (3*DD)          // 3072
#define K3M (3*MLP)         // 12288

// ---------------- scratch (device globals; no allocation allowed) ------
// packed bf16 activations: A' = [hi | lo | hi] along K
__device__ __align__(256) __nv_bfloat16 g_xnp[(size_t)MM * K3D];
__device__ __align__(256) __nv_bfloat16 g_ap [(size_t)MM * K3D];
__device__ __align__(256) __nv_bfloat16 g_hp [(size_t)MM * K3M];
__device__ __align__(256) float g_q[(size_t)MM * DD];
__device__ __align__(256) float g_k[(size_t)MM * DD];
__device__ __align__(256) float g_v[(size_t)MM * DD];
__device__ __align__(256) float g_x[(size_t)MM * DD];
// packed transposed weights: B' = [hi | hi | lo] along K,  [N][3K]
__device__ __align__(256) __nv_bfloat16 g_wqp[(size_t)DD * K3D];
__device__ __align__(256) __nv_bfloat16 g_wkp[(size_t)DD * K3D];
__device__ __align__(256) __nv_bfloat16 g_wvp[(size_t)DD * K3D];
__device__ __align__(256) __nv_bfloat16 g_wop[(size_t)DD * K3D];
__device__ __align__(256) __nv_bfloat16 g_fcp[(size_t)MLP * K3D];
__device__ __align__(256) __nv_bfloat16 g_pjp[(size_t)DD * K3M];

// ================= PTX helpers (compute_103-safe: sm_80+ features) =====
__device__ __forceinline__ uint32_t smem_u32(const void* p) {
    uint32_t a;
    asm("{ .reg .u64 t; cvta.to.shared.u64 t, %1; cvt.u32.u64 %0, t; }" : "=r"(a) : "l"(p));
    return a;
}
__device__ __forceinline__ void cp16(uint32_t sdst, const void* gsrc) {
    asm volatile("cp.async.cg.shared.global [%0], [%1], 16;" :: "r"(sdst), "l"(gsrc) : "memory");
}
__device__ __forceinline__ void ldm4(uint32_t* r, uint32_t a) {
    asm volatile("ldmatrix.sync.aligned.m8n8.x4.shared.b16 {%0,%1,%2,%3}, [%4];"
        : "=r"(r[0]), "=r"(r[1]), "=r"(r[2]), "=r"(r[3]) : "r"(a));
}
__device__ __forceinline__ void mma16816(float* d, const uint32_t* a, const uint32_t* b) {
    asm volatile("mma.sync.aligned.m16n8k16.row.col.f32.bf16.bf16.f32 "
        "{%0,%1,%2,%3},{%4,%5,%6,%7},{%8,%9},{%0,%1,%2,%3};"
        : "+f"(d[0]), "+f"(d[1]), "+f"(d[2]), "+f"(d[3])
        : "r"(a[0]), "r"(a[1]), "r"(a[2]), "r"(a[3]), "r"(b[0]), "r"(b[1]));
}

// ================= HMMA GEMM: C[M,N] = A[M,Keff] @ B[N,Keff]^T =========
// CTA tile 128x256, 16 warps (4m x 4n) of 32x64, BKC=64, 3 stages, 512 thr.
// EPI: 0 = +bias (fp32), 1 = +bias+R (fp32), 2 = gelu(+bias) -> packed bf16
#define BM 128
#define BN 256
#define BKC 64
#define PITCHB 144                     // bytes per smem row (128B data + 16B pad)
#define A_SB (128 * PITCHB)            // 18432
#define B_SB (256 * PITCHB)            // 36864
#define STAGE_SB (A_SB + B_SB)         // 55296
#define NSTAGE 3
#define SMEM_BYTES (NSTAGE * STAGE_SB) // 165888
#define NTHR 512

template<int EPI>
__global__ __launch_bounds__(NTHR, 1) void mma_gemm(
    const __nv_bfloat16* __restrict__ A, const __nv_bfloat16* __restrict__ B,
    const float* __restrict__ bias, const float* __restrict__ Rres,
    float* __restrict__ Cf, __nv_bfloat16* __restrict__ Cp,
    int M, int N, int Keff)
{
    extern __shared__ char smem[];
    const uint32_t sb = smem_u32(smem);
    const int tid = threadIdx.x;
    const int bm = blockIdx.y * BM, bn = blockIdx.x * BN;
    const int w = tid >> 5, lane = tid & 31;
    const int wm = w & 3, wn = w >> 2;       // warp grid 4(m) x 4(n), 32x64 tiles

    float acc[2][8][4];
    #pragma unroll
    for (int i = 0; i < 2; i++)
        #pragma unroll
        for (int j = 0; j < 8; j++)
            #pragma unroll
            for (int t = 0; t < 4; t++) acc[i][j][t] = 0.f;

    const int KC = Keff / BKC;

    auto load_stage = [&](int st, int c) {
        const uint32_t s0 = sb + st * STAGE_SB;
        const int k0 = c * BKC;
        #pragma unroll
        for (int i = 0; i < 2; i++) {               // A: 1024 chunks
            const int idx = tid + i * NTHR;
            const int r = idx >> 3, ch = idx & 7;
            cp16(s0 + r * PITCHB + ch * 16,
                 A + (size_t)(bm + r) * Keff + k0 + ch * 8);
        }
        #pragma unroll
        for (int i = 0; i < 4; i++) {               // B: 2048 chunks
            const int idx = tid + i * NTHR;
            const int r = idx >> 3, ch = idx & 7;
            cp16(s0 + A_SB + r * PITCHB + ch * 16,
                 B + (size_t)(bn + r) * Keff + k0 + ch * 8);
        }
        asm volatile("cp.async.commit_group;" ::: "memory");
    };

    load_stage(0, 0);
    load_stage(1, 1);

    for (int c = 0; c < KC; c++) {
        const int st = c % NSTAGE;
        asm volatile("cp.async.wait_group 1;" ::: "memory");
        __syncthreads();

        if (c + 2 < KC) load_stage((c + 2) % NSTAGE, c + 2);
        else asm volatile("cp.async.commit_group;" ::: "memory");

        const uint32_t sA = sb + st * STAGE_SB;
        const uint32_t sB = sA + A_SB;

        #pragma unroll
        for (int ks = 0; ks < 4; ks++) {
            const int kc = ks * 16;
            uint32_t afr[2][4], bfr[8][2];
            #pragma unroll
            for (int mt = 0; mt < 2; mt++) {
                const int row = wm * 32 + mt * 16 + (lane & 15);
                const int col = kc + (lane >> 4) * 8;
                ldm4(afr[mt], sA + row * PITCHB + col * 2);
            }
            #pragma unroll
            for (int np = 0; np < 4; np++) {
                const int n = wn * 64 + np * 16 + ((lane >> 4) & 1) * 8 + (lane & 7);
                const int col = kc + ((lane >> 3) & 1) * 8;
                uint32_t r[4];
                ldm4(r, sB + n * PITCHB + col * 2);
                bfr[2 * np][0] = r[0]; bfr[2 * np][1] = r[1];
                bfr[2 * np + 1][0] = r[2]; bfr[2 * np + 1][1] = r[3];
            }
            #pragma unroll
            for (int mt = 0; mt < 2; mt++)
                #pragma unroll
                for (int nt = 0; nt < 8; nt++)
                    mma16816(acc[mt][nt], afr[mt], bfr[nt]);
        }
    }

    // -------- epilogue --------
    const int r0 = lane >> 2, cp2 = (lane & 3) * 2;
    #pragma unroll
    for (int mt = 0; mt < 2; mt++) {
        #pragma unroll
        for (int nt = 0; nt < 8; nt++) {
            const int col = bn + wn * 64 + nt * 8 + cp2;
            const float2 bv = *(const float2*)(bias + col);
            #pragma unroll
            for (int half = 0; half < 2; half++) {
                const int row = bm + wm * 32 + mt * 16 + r0 + half * 8;
                float v0 = acc[mt][nt][2 * half + 0] + bv.x;
                float v1 = acc[mt][nt][2 * half + 1] + bv.y;
                if (EPI == 1) {
                    const float2 rv = *(const float2*)(Rres + (size_t)row * N + col);
                    v0 += rv.x; v1 += rv.y;
                }
                if (EPI == 2) {
                    v0 = 0.5f * v0 * (1.0f + erff(v0 * 0.70710678118654752f));
                    v1 = 0.5f * v1 * (1.0f + erff(v1 * 0.70710678118654752f));
                    const __nv_bfloat16 h0 = __float2bfloat16(v0);
                    const __nv_bfloat16 h1 = __float2bfloat16(v1);
                    const __nv_bfloat16 l0 = __float2bfloat16(v0 - __bfloat162float(h0));
                    const __nv_bfloat16 l1 = __float2bfloat16(v1 - __bfloat162float(h1));
                    const size_t o = (size_t)row * (3 * (size_t)N) + col;
                    *(__nv_bfloat162*)(Cp + o)         = __nv_bfloat162(h0, h1);
                    *(__nv_bfloat162*)(Cp + o + N)     = __nv_bfloat162(l0, l1);
                    *(__nv_bfloat162*)(Cp + o + 2 * N) = __nv_bfloat162(h0, h1);
                } else {
                    *(float2*)(Cf + (size_t)row * N + col) = make_float2(v0, v1);
                }
            }
        }
    }
}

// ---------------- weight transpose + pack: W[K][N] -> T[N][3K] ---------
// T = [hi | hi | lo]
__global__ __launch_bounds__(256) void transpose_pack(
    const float* __restrict__ W, __nv_bfloat16* __restrict__ T, int K, int N)
{
    __shared__ float t[32][33];
    const int n0 = blockIdx.x * 32, k0 = blockIdx.y * 32;
    const int tx = threadIdx.x & 31, ty = threadIdx.x >> 5;  // 32 x 8
    #pragma unroll
    for (int i = 0; i < 32; i += 8)
        t[ty + i][tx] = W[(size_t)(k0 + ty + i) * N + n0 + tx];
    __syncthreads();
    #pragma unroll
    for (int i = 0; i < 32; i += 8) {
        const float v = t[tx][ty + i];
        const __nv_bfloat16 h = __float2bfloat16(v);
        const __nv_bfloat16 l = __float2bfloat16(v - __bfloat162float(h));
        const size_t o = (size_t)(n0 + ty + i) * (3 * (size_t)K) + k0 + tx;
        T[o]         = h;
        T[o + K]     = h;
        T[o + 2 * K] = l;
    }
}

// ---------------- LayerNorm -> packed bf16 [hi|lo|hi] ------------------
__global__ __launch_bounds__(256) void ln_pack_kernel(
    const float* __restrict__ X, const float* __restrict__ w,
    const float* __restrict__ b, __nv_bfloat16* __restrict__ Yp)
{
    const int row = blockIdx.x;
    const int tid = threadIdx.x;
    const float* x = X + (size_t)row * DD;

    float4 xv = *(const float4*)(x + tid * 4);
    float s  = xv.x + xv.y + xv.z + xv.w;
    float s2 = fmaf(xv.x, xv.x, fmaf(xv.y, xv.y, fmaf(xv.z, xv.z, xv.w * xv.w)));
    #pragma unroll
    for (int o = 16; o; o >>= 1) {
        s  += __shfl_xor_sync(0xFFFFFFFFu, s,  o);
        s2 += __shfl_xor_sync(0xFFFFFFFFu, s2, o);
    }
    __shared__ float sh[8], sh2[8];
    const int lane = tid & 31, wid = tid >> 5;
    if (lane == 0) { sh[wid] = s; sh2[wid] = s2; }
    __syncthreads();
    float S = 0.f, S2 = 0.f;
    #pragma unroll
    for (int i = 0; i < 8; i++) { S += sh[i]; S2 += sh2[i]; }
    const float mean = S * (1.0f / DD);
    const float var  = S2 * (1.0f / DD) - mean * mean;
    const float inv  = rsqrtf(var + 1e-5f);

    float4 wv = *(const float4*)(w + tid * 4);
    float4 bv = *(const float4*)(b + tid * 4);
    float y[4];
    y[0] = (xv.x - mean) * inv * wv.x + bv.x;
    y[1] = (xv.y - mean) * inv * wv.y + bv.y;
    y[2] = (xv.z - mean) * inv * wv.z + bv.z;
    y[3] = (xv.w - mean) * inv * wv.w + bv.w;

    __nv_bfloat16 h[4], l[4];
    #pragma unroll
    for (int t = 0; t < 4; t++) {
        h[t] = __float2bfloat16(y[t]);
        l[t] = __float2bfloat16(y[t] - __bfloat162float(h[t]));
    }
    const size_t o = (size_t)row * K3D + tid * 4;
    *(__nv_bfloat162*)(Yp + o)              = __nv_bfloat162(h[0], h[1]);
    *(__nv_bfloat162*)(Yp + o + 2)          = __nv_bfloat162(h[2], h[3]);
    *(__nv_bfloat162*)(Yp + o + DD)         = __nv_bfloat162(l[0], l[1]);
    *(__nv_bfloat162*)(Yp + o + DD + 2)     = __nv_bfloat162(l[2], l[3]);
    *(__nv_bfloat162*)(Yp + o + 2 * DD)     = __nv_bfloat162(h[0], h[1]);
    *(__nv_bfloat162*)(Yp + o + 2 * DD + 2) = __nv_bfloat162(h[2], h[3]);
}

// ---------------- fused per-token linear attention -> packed bf16 ------
__device__ __forceinline__ float elu1(float x) {
    return x > 0.f ? x + 1.0f : expf(x);
}

__global__ __launch_bounds__(256) void attn_kernel(
    const float* __restrict__ Q, const float* __restrict__ K_,
    const float* __restrict__ V, __nv_bfloat16* __restrict__ Op)
{
    __shared__ float fq[HH][HD];
    __shared__ float fk[HH][HD];
    __shared__ float vv[HH][HD];
    __shared__ float kv[HD][HD];
    __shared__ float ksum[HD];

    const size_t base  = (size_t)blockIdx.x * DD;
    const size_t base3 = (size_t)blockIdx.x * K3D;
    const int tid = threadIdx.x;

    {
        float4 q4 = *(const float4*)(Q  + base + tid * 4);
        float4 k4 = *(const float4*)(K_ + base + tid * 4);
        float4 v4 = *(const float4*)(V  + base + tid * 4);
        float* fqf = &fq[0][0]; float* fkf = &fk[0][0]; float* vvf = &vv[0][0];
        fqf[tid*4+0] = elu1(q4.x); fqf[tid*4+1] = elu1(q4.y);
        fqf[tid*4+2] = elu1(q4.z); fqf[tid*4+3] = elu1(q4.w);
        fkf[tid*4+0] = elu1(k4.x); fkf[tid*4+1] = elu1(k4.y);
        fkf[tid*4+2] = elu1(k4.z); fkf[tid*4+3] = elu1(k4.w);
        vvf[tid*4+0] = v4.x; vvf[tid*4+1] = v4.y;
        vvf[tid*4+2] = v4.z; vvf[tid*4+3] = v4.w;
    }
    __syncthreads();

    if (tid < HD) {
        float s = 0.f;
        #pragma unroll
        for (int h = 0; h < HH; h++) s += fk[h][tid];
        ksum[tid] = s;
    }
    {
        const int e = tid & 63;
        const int d0 = tid >> 6;
        #pragma unroll
        for (int j = 0; j < 16; j++) {
            const int d = d0 + j * 4;
            float s = 0.f;
            #pragma unroll
            for (int h = 0; h < HH; h++) s = fmaf(fk[h][d], vv[h][e], s);
            kv[d][e] = s;
        }
    }
    __syncthreads();
    {
        const int e = tid & 63;
        const int h0 = tid >> 6;
        #pragma unroll
        for (int j = 0; j < 4; j++) {
            const int h = h0 + j * 4;
            float s = 0.f, sq = 0.f;
            #pragma unroll
            for (int d = 0; d < HD; d++) {
                const float f = fq[h][d];
                s  = fmaf(f, kv[d][e], s);
                sq = fmaf(f, ksum[d], sq);
            }
            const float val = s / (sq + 1e-6f);
            const __nv_bfloat16 hi = __float2bfloat16(val);
            const __nv_bfloat16 lo = __float2bfloat16(val - __bfloat162float(hi));
            const size_t o = base3 + h * HD + e;
            Op[o]          = hi;
            Op[o + DD]     = lo;
            Op[o + 2 * DD] = hi;
        }
    }
}

// ---------------- launch ----------------
extern "C" void kernel_launch(void* const* d_in, const int* in_sizes, int n_in,
                              void* d_out, int out_size)
{
    const float* q_x    = (const float*)d_in[0];
    const float* ln1_w  = (const float*)d_in[1];
    const float* ln1_b  = (const float*)d_in[2];
    const float* wq     = (const float*)d_in[3];
    const float* bq     = (const float*)d_in[4];
    const float* wk     = (const float*)d_in[5];
    const float* bk     = (const float*)d_in[6];
    const float* wv     = (const float*)d_in[7];
    const float* bv     = (const float*)d_in[8];
    const float* wo     = (const float*)d_in[9];
    const float* bo     = (const float*)d_in[10];
    const float* ln2_w  = (const float*)d_in[11];
    const float* ln2_b  = (const float*)d_in[12];
    const float* fc_w   = (const float*)d_in[13];
    const float* fc_b   = (const float*)d_in[14];
    const float* proj_w = (const float*)d_in[15];
    const float* proj_b = (const float*)d_in[16];
    float* out = (float*)d_out;

    __nv_bfloat16 *xnp, *ap, *hp, *wqp, *wkp, *wvp, *wop, *fcp, *pjp;
    float *q, *k, *v, *x;
    cudaGetSymbolAddress((void**)&xnp, g_xnp);
    cudaGetSymbolAddress((void**)&ap,  g_ap);
    cudaGetSymbolAddress((void**)&hp,  g_hp);
    cudaGetSymbolAddress((void**)&q,   g_q);
    cudaGetSymbolAddress((void**)&k,   g_k);
    cudaGetSymbolAddress((void**)&v,   g_v);
    cudaGetSymbolAddress((void**)&x,   g_x);
    cudaGetSymbolAddress((void**)&wqp, g_wqp);
    cudaGetSymbolAddress((void**)&wkp, g_wkp);
    cudaGetSymbolAddress((void**)&wvp, g_wvp);
    cudaGetSymbolAddress((void**)&wop, g_wop);
    cudaGetSymbolAddress((void**)&fcp, g_fcp);
    cudaGetSymbolAddress((void**)&pjp, g_pjp);

    cudaFuncSetAttribute(mma_gemm<0>, cudaFuncAttributeMaxDynamicSharedMemorySize, SMEM_BYTES);
    cudaFuncSetAttribute(mma_gemm<1>, cudaFuncAttributeMaxDynamicSharedMemorySize, SMEM_BYTES);
    cudaFuncSetAttribute(mma_gemm<2>, cudaFuncAttributeMaxDynamicSharedMemorySize, SMEM_BYTES);

    // weight prep: transpose + bf16 hi/lo pack  [N][3K]
    transpose_pack<<<dim3(DD/32,  DD/32),  256>>>(wq,     wqp, DD,  DD);
    transpose_pack<<<dim3(DD/32,  DD/32),  256>>>(wk,     wkp, DD,  DD);
    transpose_pack<<<dim3(DD/32,  DD/32),  256>>>(wv,     wvp, DD,  DD);
    transpose_pack<<<dim3(DD/32,  DD/32),  256>>>(wo,     wop, DD,  DD);
    transpose_pack<<<dim3(MLP/32, DD/32),  256>>>(fc_w,   fcp, DD,  MLP);
    transpose_pack<<<dim3(DD/32,  MLP/32), 256>>>(proj_w, pjp, MLP, DD);

    const dim3 gD (DD  / BN, MM / BM);   // (4, 128)
    const dim3 gML(MLP / BN, MM / BM);   // (16, 128)

    // 1) xn = LN1(q_x) -> packed bf16
    ln_pack_kernel<<<MM, 256>>>(q_x, ln1_w, ln1_b, xnp);
    // 2) q/k/v = xn @ w* + b*  (fp32 out)
    mma_gemm<0><<<gD, NTHR, SMEM_BYTES>>>(xnp, wqp, bq, nullptr, q, nullptr, MM, DD, K3D);
    mma_gemm<0><<<gD, NTHR, SMEM_BYTES>>>(xnp, wkp, bk, nullptr, k, nullptr, MM, DD, K3D);
    mma_gemm<0><<<gD, NTHR, SMEM_BYTES>>>(xnp, wvp, bv, nullptr, v, nullptr, MM, DD, K3D);
    // 3) fused per-token linear attention -> packed bf16
    attn_kernel<<<MM, 256>>>(q, k, v, ap);
    // 4) x = q_x + attn @ wo + bo  (fp32 out)
    mma_gemm<1><<<gD, NTHR, SMEM_BYTES>>>(ap, wop, bo, q_x, x, nullptr, MM, DD, K3D);
    // 5) xn2 = LN2(x) -> packed bf16
    ln_pack_kernel<<<MM, 256>>>(x, ln2_w, ln2_b, xnp);
    // 6) h = gelu(xn2 @ fc_w + fc_b) -> packed bf16
    mma_gemm<2><<<gML, NTHR, SMEM_BYTES>>>(xnp, fcp, fc_b, nullptr, nullptr, hp, MM, MLP, K3D);
    // 7) out = x + h @ proj_w + proj_b  (fp32 out)
    mma_gemm<1><<<gD, NTHR, SMEM_BYTES>>>(hp, pjp, proj_b, x, out, nullptr, MM, DD, K3M);
}

// round 11
// speedup vs baseline: 1.1510x; 1.1344x over previous
#include <cuda_runtime.h>
#include <cuda_bf16.h>
#include <math.h>
#include <stdint.h>

// ---------------- problem constants ----------------
#define BB 4
#define NN 4096
#define DD 1024
#define HH 16
#define HD 64
#define MLP 4096
#define MM (BB*NN)          // 16384 rows
#define K3D (3*DD)          // 3072
#define K3M (3*MLP)         // 12288

// ---------------- scratch (device globals; no allocation allowed) ------
// packed bf16 activations: A' = [hi | lo | hi] along K
__device__ __align__(256) __nv_bfloat16 g_xnp[(size_t)MM * K3D];
__device__ __align__(256) __nv_bfloat16 g_ap [(size_t)MM * K3D];
__device__ __align__(256) __nv_bfloat16 g_hp [(size_t)MM * K3M];
__device__ __align__(256) float g_q[(size_t)MM * DD];
__device__ __align__(256) float g_k[(size_t)MM * DD];
__device__ __align__(256) float g_v[(size_t)MM * DD];
__device__ __align__(256) float g_x[(size_t)MM * DD];
// packed transposed weights: B' = [hi | hi | lo] along K,  [N][3K]
__device__ __align__(256) __nv_bfloat16 g_wqp[(size_t)DD * K3D];
__device__ __align__(256) __nv_bfloat16 g_wkp[(size_t)DD * K3D];
__device__ __align__(256) __nv_bfloat16 g_wvp[(size_t)DD * K3D];
__device__ __align__(256) __nv_bfloat16 g_wop[(size_t)DD * K3D];
__device__ __align__(256) __nv_bfloat16 g_fcp[(size_t)MLP * K3D];
__device__ __align__(256) __nv_bfloat16 g_pjp[(size_t)DD * K3M];

// ================= PTX helpers (compute_103-safe: sm_80+ features) =====
__device__ __forceinline__ uint32_t smem_u32(const void* p) {
    uint32_t a;
    asm("{ .reg .u64 t; cvta.to.shared.u64 t, %1; cvt.u32.u64 %0, t; }" : "=r"(a) : "l"(p));
    return a;
}
__device__ __forceinline__ void cp16(uint32_t sdst, const void* gsrc) {
    asm volatile("cp.async.cg.shared.global [%0], [%1], 16;" :: "r"(sdst), "l"(gsrc) : "memory");
}
__device__ __forceinline__ void ldm4(uint32_t* r, uint32_t a) {
    asm volatile("ldmatrix.sync.aligned.m8n8.x4.shared.b16 {%0,%1,%2,%3}, [%4];"
        : "=r"(r[0]), "=r"(r[1]), "=r"(r[2]), "=r"(r[3]) : "r"(a));
}
__device__ __forceinline__ void mma16816(float* d, const uint32_t* a, const uint32_t* b) {
    asm volatile("mma.sync.aligned.m16n8k16.row.col.f32.bf16.bf16.f32 "
        "{%0,%1,%2,%3},{%4,%5,%6,%7},{%8,%9},{%0,%1,%2,%3};"
        : "+f"(d[0]), "+f"(d[1]), "+f"(d[2]), "+f"(d[3])
        : "r"(a[0]), "r"(a[1]), "r"(a[2]), "r"(a[3]), "r"(b[0]), "r"(b[1]));
}

// ================= HMMA GEMM: C[M,N] = A[M,Keff] @ B[N,Keff]^T =========
// CTA 128x128, 8 warps (2m x 4n) of 64x32, BKC=64, 3 stages, 2 CTA/SM.
// EPI: 0 = +bias (fp32), 1 = +bias+R (fp32), 2 = gelu(+bias) -> packed bf16
#define BM 128
#define BN 128
#define BKC 64
#define PITCHB 144                     // bytes per smem row (128B data + 16B pad)
#define TILE_SB (128 * PITCHB)         // 18432
#define STAGE_SB (2 * TILE_SB)         // 36864
#define NSTAGE 3
#define SMEM_BYTES (NSTAGE * STAGE_SB) // 110592 per CTA; x2 CTA = 216KB/SM

template<int EPI>
__global__ __launch_bounds__(256, 2) void mma_gemm(
    const __nv_bfloat16* __restrict__ A, const __nv_bfloat16* __restrict__ B,
    const float* __restrict__ bias, const float* __restrict__ Rres,
    float* __restrict__ Cf, __nv_bfloat16* __restrict__ Cp,
    int M, int N, int Keff)
{
    extern __shared__ char smem[];
    const uint32_t sb = smem_u32(smem);
    const int tid = threadIdx.x;
    const int bm = blockIdx.y * BM, bn = blockIdx.x * BN;
    const int w = tid >> 5, lane = tid & 31;
    const int wm = w & 1, wn = w >> 1;       // warp grid 2(m) x 4(n), 64x32 tiles

    float acc[4][4][4];
    #pragma unroll
    for (int i = 0; i < 4; i++)
        #pragma unroll
        for (int j = 0; j < 4; j++)
            #pragma unroll
            for (int t = 0; t < 4; t++) acc[i][j][t] = 0.f;

    const int KC = Keff / BKC;

    auto load_stage = [&](int st, int c) {
        const uint32_t s0 = sb + st * STAGE_SB;
        const int k0 = c * BKC;
        #pragma unroll
        for (int i = 0; i < 4; i++) {               // A: 1024 16B chunks
            const int idx = tid + i * 256;
            const int r = idx >> 3, ch = idx & 7;
            cp16(s0 + r * PITCHB + ch * 16,
                 A + (size_t)(bm + r) * Keff + k0 + ch * 8);
        }
        #pragma unroll
        for (int i = 0; i < 4; i++) {               // B: 1024 16B chunks
            const int idx = tid + i * 256;
            const int r = idx >> 3, ch = idx & 7;
            cp16(s0 + TILE_SB + r * PITCHB + ch * 16,
                 B + (size_t)(bn + r) * Keff + k0 + ch * 8);
        }
        asm volatile("cp.async.commit_group;" ::: "memory");
    };

    load_stage(0, 0);
    load_stage(1, 1);

    for (int c = 0; c < KC; c++) {
        const int st = c % NSTAGE;
        asm volatile("cp.async.wait_group 1;" ::: "memory");
        __syncthreads();

        if (c + 2 < KC) load_stage((c + 2) % NSTAGE, c + 2);
        else asm volatile("cp.async.commit_group;" ::: "memory");

        const uint32_t sA = sb + st * STAGE_SB;
        const uint32_t sB = sA + TILE_SB;

        #pragma unroll
        for (int ks = 0; ks < 4; ks++) {
            const int kc = ks * 16;
            uint32_t afr[4][4], bfr[4][2];
            #pragma unroll
            for (int mt = 0; mt < 4; mt++) {
                const int row = wm * 64 + mt * 16 + (lane & 15);
                const int col = kc + (lane >> 4) * 8;
                ldm4(afr[mt], sA + row * PITCHB + col * 2);
            }
            #pragma unroll
            for (int np = 0; np < 2; np++) {
                const int n = wn * 32 + np * 16 + ((lane >> 4) & 1) * 8 + (lane & 7);
                const int col = kc + ((lane >> 3) & 1) * 8;
                uint32_t r[4];
                ldm4(r, sB + n * PITCHB + col * 2);
                bfr[2 * np][0] = r[0]; bfr[2 * np][1] = r[1];
                bfr[2 * np + 1][0] = r[2]; bfr[2 * np + 1][1] = r[3];
            }
            #pragma unroll
            for (int mt = 0; mt < 4; mt++)
                #pragma unroll
                for (int nt = 0; nt < 4; nt++)
                    mma16816(acc[mt][nt], afr[mt], bfr[nt]);
        }
    }

    // -------- epilogue --------
    const int r0 = lane >> 2, cp2 = (lane & 3) * 2;
    #pragma unroll
    for (int mt = 0; mt < 4; mt++) {
        #pragma unroll
        for (int nt = 0; nt < 4; nt++) {
            const int col = bn + wn * 32 + nt * 8 + cp2;
            const float2 bv = *(const float2*)(bias + col);
            #pragma unroll
            for (int half = 0; half < 2; half++) {
                const int row = bm + wm * 64 + mt * 16 + r0 + half * 8;
                float v0 = acc[mt][nt][2 * half + 0] + bv.x;
                float v1 = acc[mt][nt][2 * half + 1] + bv.y;
                if (EPI == 1) {
                    const float2 rv = *(const float2*)(Rres + (size_t)row * N + col);
                    v0 += rv.x; v1 += rv.y;
                }
                if (EPI == 2) {
                    v0 = 0.5f * v0 * (1.0f + erff(v0 * 0.70710678118654752f));
                    v1 = 0.5f * v1 * (1.0f + erff(v1 * 0.70710678118654752f));
                    const __nv_bfloat16 h0 = __float2bfloat16(v0);
                    const __nv_bfloat16 h1 = __float2bfloat16(v1);
                    const __nv_bfloat16 l0 = __float2bfloat16(v0 - __bfloat162float(h0));
                    const __nv_bfloat16 l1 = __float2bfloat16(v1 - __bfloat162float(h1));
                    const size_t o = (size_t)row * (3 * (size_t)N) + col;
                    *(__nv_bfloat162*)(Cp + o)         = __nv_bfloat162(h0, h1);
                    *(__nv_bfloat162*)(Cp + o + N)     = __nv_bfloat162(l0, l1);
                    *(__nv_bfloat162*)(Cp + o + 2 * N) = __nv_bfloat162(h0, h1);
                } else {
                    *(float2*)(Cf + (size_t)row * N + col) = make_float2(v0, v1);
                }
            }
        }
    }
}

// ---------------- weight transpose + pack: W[K][N] -> T[N][3K] ---------
// T = [hi | hi | lo]
__global__ __launch_bounds__(256) void transpose_pack(
    const float* __restrict__ W, __nv_bfloat16* __restrict__ T, int K, int N)
{
    __shared__ float t[32][33];
    const int n0 = blockIdx.x * 32, k0 = blockIdx.y * 32;
    const int tx = threadIdx.x & 31, ty = threadIdx.x >> 5;  // 32 x 8
    #pragma unroll
    for (int i = 0; i < 32; i += 8)
        t[ty + i][tx] = W[(size_t)(k0 + ty + i) * N + n0 + tx];
    __syncthreads();
    #pragma unroll
    for (int i = 0; i < 32; i += 8) {
        const float v = t[tx][ty + i];
        const __nv_bfloat16 h = __float2bfloat16(v);
        const __nv_bfloat16 l = __float2bfloat16(v - __bfloat162float(h));
        const size_t o = (size_t)(n0 + ty + i) * (3 * (size_t)K) + k0 + tx;
        T[o]         = h;
        T[o + K]     = h;
        T[o + 2 * K] = l;
    }
}

// ---------------- LayerNorm -> packed bf16 [hi|lo|hi] ------------------
__global__ __launch_bounds__(256) void ln_pack_kernel(
    const float* __restrict__ X, const float* __restrict__ w,
    const float* __restrict__ b, __nv_bfloat16* __restrict__ Yp)
{
    const int row = blockIdx.x;
    const int tid = threadIdx.x;
    const float* x = X + (size_t)row * DD;

    float4 xv = *(const float4*)(x + tid * 4);
    float s  = xv.x + xv.y + xv.z + xv.w;
    float s2 = fmaf(xv.x, xv.x, fmaf(xv.y, xv.y, fmaf(xv.z, xv.z, xv.w * xv.w)));
    #pragma unroll
    for (int o = 16; o; o >>= 1) {
        s  += __shfl_xor_sync(0xFFFFFFFFu, s,  o);
        s2 += __shfl_xor_sync(0xFFFFFFFFu, s2, o);
    }
    __shared__ float sh[8], sh2[8];
    const int lane = tid & 31, wid = tid >> 5;
    if (lane == 0) { sh[wid] = s; sh2[wid] = s2; }
    __syncthreads();
    float S = 0.f, S2 = 0.f;
    #pragma unroll
    for (int i = 0; i < 8; i++) { S += sh[i]; S2 += sh2[i]; }
    const float mean = S * (1.0f / DD);
    const float var  = S2 * (1.0f / DD) - mean * mean;
    const float inv  = rsqrtf(var + 1e-5f);

    float4 wv = *(const float4*)(w + tid * 4);
    float4 bv = *(const float4*)(b + tid * 4);
    float y[4];
    y[0] = (xv.x - mean) * inv * wv.x + bv.x;
    y[1] = (xv.y - mean) * inv * wv.y + bv.y;
    y[2] = (xv.z - mean) * inv * wv.z + bv.z;
    y[3] = (xv.w - mean) * inv * wv.w + bv.w;

    __nv_bfloat16 h[4], l[4];
    #pragma unroll
    for (int t = 0; t < 4; t++) {
        h[t] = __float2bfloat16(y[t]);
        l[t] = __float2bfloat16(y[t] - __bfloat162float(h[t]));
    }
    const size_t o = (size_t)row * K3D + tid * 4;
    *(__nv_bfloat162*)(Yp + o)              = __nv_bfloat162(h[0], h[1]);
    *(__nv_bfloat162*)(Yp + o + 2)          = __nv_bfloat162(h[2], h[3]);
    *(__nv_bfloat162*)(Yp + o + DD)         = __nv_bfloat162(l[0], l[1]);
    *(__nv_bfloat162*)(Yp + o + DD + 2)     = __nv_bfloat162(l[2], l[3]);
    *(__nv_bfloat162*)(Yp + o + 2 * DD)     = __nv_bfloat162(h[0], h[1]);
    *(__nv_bfloat162*)(Yp + o + 2 * DD + 2) = __nv_bfloat162(h[2], h[3]);
}

// ---------------- fused per-token linear attention -> packed bf16 ------
__device__ __forceinline__ float elu1(float x) {
    return x > 0.f ? x + 1.0f : expf(x);
}

__global__ __launch_bounds__(256) void attn_kernel(
    const float* __restrict__ Q, const float* __restrict__ K_,
    const float* __restrict__ V, __nv_bfloat16* __restrict__ Op)
{
    __shared__ float fq[HH][HD];
    __shared__ float fk[HH][HD];
    __shared__ float vv[HH][HD];
    __shared__ float kv[HD][HD];
    __shared__ float ksum[HD];

    const size_t base  = (size_t)blockIdx.x * DD;
    const size_t base3 = (size_t)blockIdx.x * K3D;
    const int tid = threadIdx.x;

    {
        float4 q4 = *(const float4*)(Q  + base + tid * 4);
        float4 k4 = *(const float4*)(K_ + base + tid * 4);
        float4 v4 = *(const float4*)(V  + base + tid * 4);
        float* fqf = &fq[0][0]; float* fkf = &fk[0][0]; float* vvf = &vv[0][0];
        fqf[tid*4+0] = elu1(q4.x); fqf[tid*4+1] = elu1(q4.y);
        fqf[tid*4+2] = elu1(q4.z); fqf[tid*4+3] = elu1(q4.w);
        fkf[tid*4+0] = elu1(k4.x); fkf[tid*4+1] = elu1(k4.y);
        fkf[tid*4+2] = elu1(k4.z); fkf[tid*4+3] = elu1(k4.w);
        vvf[tid*4+0] = v4.x; vvf[tid*4+1] = v4.y;
        vvf[tid*4+2] = v4.z; vvf[tid*4+3] = v4.w;
    }
    __syncthreads();

    if (tid < HD) {
        float s = 0.f;
        #pragma unroll
        for (int h = 0; h < HH; h++) s += fk[h][tid];
        ksum[tid] = s;
    }
    {
        const int e = tid & 63;
        const int d0 = tid >> 6;
        #pragma unroll
        for (int j = 0; j < 16; j++) {
            const int d = d0 + j * 4;
            float s = 0.f;
            #pragma unroll
            for (int h = 0; h < HH; h++) s = fmaf(fk[h][d], vv[h][e], s);
            kv[d][e] = s;
        }
    }
    __syncthreads();
    {
        const int e = tid & 63;
        const int h0 = tid >> 6;
        #pragma unroll
        for (int j = 0; j < 4; j++) {
            const int h = h0 + j * 4;
            float s = 0.f, sq = 0.f;
            #pragma unroll
            for (int d = 0; d < HD; d++) {
                const float f = fq[h][d];
                s  = fmaf(f, kv[d][e], s);
                sq = fmaf(f, ksum[d], sq);
            }
            const float val = s / (sq + 1e-6f);
            const __nv_bfloat16 hi = __float2bfloat16(val);
            const __nv_bfloat16 lo = __float2bfloat16(val - __bfloat162float(hi));
            const size_t o = base3 + h * HD + e;
            Op[o]          = hi;
            Op[o + DD]     = lo;
            Op[o + 2 * DD] = hi;
        }
    }
}

// ---------------- launch ----------------
extern "C" void kernel_launch(void* const* d_in, const int* in_sizes, int n_in,
                              void* d_out, int out_size)
{
    const float* q_x    = (const float*)d_in[0];
    const float* ln1_w  = (const float*)d_in[1];
    const float* ln1_b  = (const float*)d_in[2];
    const float* wq     = (const float*)d_in[3];
    const float* bq     = (const float*)d_in[4];
    const float* wk     = (const float*)d_in[5];
    const float* bk     = (const float*)d_in[6];
    const float* wv     = (const float*)d_in[7];
    const float* bv     = (const float*)d_in[8];
    const float* wo     = (const float*)d_in[9];
    const float* bo     = (const float*)d_in[10];
    const float* ln2_w  = (const float*)d_in[11];
    const float* ln2_b  = (const float*)d_in[12];
    const float* fc_w   = (const float*)d_in[13];
    const float* fc_b   = (const float*)d_in[14];
    const float* proj_w = (const float*)d_in[15];
    const float* proj_b = (const float*)d_in[16];
    float* out = (float*)d_out;

    __nv_bfloat16 *xnp, *ap, *hp, *wqp, *wkp, *wvp, *wop, *fcp, *pjp;
    float *q, *k, *v, *x;
    cudaGetSymbolAddress((void**)&xnp, g_xnp);
    cudaGetSymbolAddress((void**)&ap,  g_ap);
    cudaGetSymbolAddress((void**)&hp,  g_hp);
    cudaGetSymbolAddress((void**)&q,   g_q);
    cudaGetSymbolAddress((void**)&k,   g_k);
    cudaGetSymbolAddress((void**)&v,   g_v);
    cudaGetSymbolAddress((void**)&x,   g_x);
    cudaGetSymbolAddress((void**)&wqp, g_wqp);
    cudaGetSymbolAddress((void**)&wkp, g_wkp);
    cudaGetSymbolAddress((void**)&wvp, g_wvp);
    cudaGetSymbolAddress((void**)&wop, g_wop);
    cudaGetSymbolAddress((void**)&fcp, g_fcp);
    cudaGetSymbolAddress((void**)&pjp, g_pjp);

    cudaFuncSetAttribute(mma_gemm<0>, cudaFuncAttributeMaxDynamicSharedMemorySize, SMEM_BYTES);
    cudaFuncSetAttribute(mma_gemm<1>, cudaFuncAttributeMaxDynamicSharedMemorySize, SMEM_BYTES);
    cudaFuncSetAttribute(mma_gemm<2>, cudaFuncAttributeMaxDynamicSharedMemorySize, SMEM_BYTES);

    // weight prep: transpose + bf16 hi/lo pack  [N][3K]
    transpose_pack<<<dim3(DD/32,  DD/32),  256>>>(wq,     wqp, DD,  DD);
    transpose_pack<<<dim3(DD/32,  DD/32),  256>>>(wk,     wkp, DD,  DD);
    transpose_pack<<<dim3(DD/32,  DD/32),  256>>>(wv,     wvp, DD,  DD);
    transpose_pack<<<dim3(DD/32,  DD/32),  256>>>(wo,     wop, DD,  DD);
    transpose_pack<<<dim3(MLP/32, DD/32),  256>>>(fc_w,   fcp, DD,  MLP);
    transpose_pack<<<dim3(DD/32,  MLP/32), 256>>>(proj_w, pjp, MLP, DD);

    const dim3 gD (DD  / BN, MM / BM);   // (8, 128)
    const dim3 gML(MLP / BN, MM / BM);   // (32, 128)

    // 1) xn = LN1(q_x) -> packed bf16
    ln_pack_kernel<<<MM, 256>>>(q_x, ln1_w, ln1_b, xnp);
    // 2) q/k/v = xn @ w* + b*  (fp32 out)
    mma_gemm<0><<<gD, 256, SMEM_BYTES>>>(xnp, wqp, bq, nullptr, q, nullptr, MM, DD, K3D);
    mma_gemm<0><<<gD, 256, SMEM_BYTES>>>(xnp, wkp, bk, nullptr, k, nullptr, MM, DD, K3D);
    mma_gemm<0><<<gD, 256, SMEM_BYTES>>>(xnp, wvp, bv, nullptr, v, nullptr, MM, DD, K3D);
    // 3) fused per-token linear attention -> packed bf16
    attn_kernel<<<MM, 256>>>(q, k, v, ap);
    // 4) x = q_x + attn @ wo + bo  (fp32 out)
    mma_gemm<1><<<gD, 256, SMEM_BYTES>>>(ap, wop, bo, q_x, x, nullptr, MM, DD, K3D);
    // 5) xn2 = LN2(x) -> packed bf16
    ln_pack_kernel<<<MM, 256>>>(x, ln2_w, ln2_b, xnp);
    // 6) h = gelu(xn2 @ fc_w + fc_b) -> packed bf16
    mma_gemm<2><<<gML, 256, SMEM_BYTES>>>(xnp, fcp, fc_b, nullptr, nullptr, hp, MM, MLP, K3D);
    // 7) out = x + h @ proj_w + proj_b  (fp32 out)
    mma_gemm<1><<<gD, 256, SMEM_BYTES>>>(hp, pjp, proj_b, x, out, nullptr, MM, DD, K3M);
}

// round 12
// speedup vs baseline: 1.4334x; 1.2454x over previous
#include <cuda_runtime.h>
#include <cuda_bf16.h>
#include <cuda_fp16.h>
#include <math.h>
#include <stdint.h>

// ---------------- problem constants ----------------
#define BB 4
#define NN 4096
#define DD 1024
#define HH 16
#define HD 64
#define MLP 4096
#define MM (BB*NN)          // 16384 rows
#define K3D (3*DD)          // 3072
#define K2D (2*DD)          // 2048
#define K2M (2*MLP)         // 8192

// ---------------- scratch (device globals; no allocation allowed) ------
// bf16 3-seg packed activations: [hi | lo | hi] along K
__device__ __align__(256) __nv_bfloat16 g_xnp[(size_t)MM * K3D];
__device__ __align__(256) __nv_bfloat16 g_ap [(size_t)MM * K3D];
// fp16 2-seg packed activations: [hi | lo]
__device__ __align__(256) __half g_xn2p[(size_t)MM * K2D];
__device__ __align__(256) __half g_hp2 [(size_t)MM * K2M];
__device__ __align__(256) float g_q[(size_t)MM * DD];
__device__ __align__(256) float g_k[(size_t)MM * DD];
__device__ __align__(256) float g_v[(size_t)MM * DD];
__device__ __align__(256) float g_x[(size_t)MM * DD];
// bf16 3-seg transposed weights [N][3K]: [hi | hi | lo]
__device__ __align__(256) __nv_bfloat16 g_wqp[(size_t)DD * K3D];
__device__ __align__(256) __nv_bfloat16 g_wkp[(size_t)DD * K3D];
__device__ __align__(256) __nv_bfloat16 g_wvp[(size_t)DD * K3D];
__device__ __align__(256) __nv_bfloat16 g_wop[(size_t)DD * K3D];
// fp16 2-seg transposed weights [N][2K]: [hi | hi] (duplicated)
__device__ __align__(256) __half g_fcp2[(size_t)MLP * K2D];
__device__ __align__(256) __half g_pjp2[(size_t)DD * K2M];

// ================= PTX helpers (compute_103-safe: sm_80+ features) =====
__device__ __forceinline__ uint32_t smem_u32(const void* p) {
    uint32_t a;
    asm("{ .reg .u64 t; cvta.to.shared.u64 t, %1; cvt.u32.u64 %0, t; }" : "=r"(a) : "l"(p));
    return a;
}
__device__ __forceinline__ void cp16(uint32_t sdst, const void* gsrc) {
    asm volatile("cp.async.cg.shared.global [%0], [%1], 16;" :: "r"(sdst), "l"(gsrc) : "memory");
}
__device__ __forceinline__ void ldm4(uint32_t* r, uint32_t a) {
    asm volatile("ldmatrix.sync.aligned.m8n8.x4.shared.b16 {%0,%1,%2,%3}, [%4];"
        : "=r"(r[0]), "=r"(r[1]), "=r"(r[2]), "=r"(r[3]) : "r"(a));
}
__device__ __forceinline__ void mma_bf(float* d, const uint32_t* a, const uint32_t* b) {
    asm volatile("mma.sync.aligned.m16n8k16.row.col.f32.bf16.bf16.f32 "
        "{%0,%1,%2,%3},{%4,%5,%6,%7},{%8,%9},{%0,%1,%2,%3};"
        : "+f"(d[0]), "+f"(d[1]), "+f"(d[2]), "+f"(d[3])
        : "r"(a[0]), "r"(a[1]), "r"(a[2]), "r"(a[3]), "r"(b[0]), "r"(b[1]));
}
__device__ __forceinline__ void mma_f16(float* d, const uint32_t* a, const uint32_t* b) {
    asm volatile("mma.sync.aligned.m16n8k16.row.col.f32.f16.f16.f32 "
        "{%0,%1,%2,%3},{%4,%5,%6,%7},{%8,%9},{%0,%1,%2,%3};"
        : "+f"(d[0]), "+f"(d[1]), "+f"(d[2]), "+f"(d[3])
        : "r"(a[0]), "r"(a[1]), "r"(a[2]), "r"(a[3]), "r"(b[0]), "r"(b[1]));
}

// ================= HMMA GEMM: C[M,N] = A[M,Keff] @ B[N,Keff]^T =========
// CTA 128x128, 8 warps (2m x 4n) of 64x32, BKC=64, 3 stages, 2 CTA/SM.
// EPI: 0 = +bias (fp32), 1 = +bias+R (fp32), 2 = gelu(+bias) -> fp16 2-seg
// FP16: 0 = bf16 operands, 1 = fp16 operands
#define BM 128
#define BN 128
#define BKC 64
#define PITCHB 144                     // bytes per smem row (128B data + 16B pad)
#define TILE_SB (128 * PITCHB)         // 18432
#define STAGE_SB (2 * TILE_SB)         // 36864
#define NSTAGE 3
#define SMEM_BYTES (NSTAGE * STAGE_SB) // 110592 per CTA; x2 CTA = 216KB/SM

template<int EPI, int FP16>
__global__ __launch_bounds__(256, 2) void mma_gemm(
    const void* __restrict__ Av, const void* __restrict__ Bv,
    const float* __restrict__ bias, const float* __restrict__ Rres,
    float* __restrict__ Cf, __half* __restrict__ Cp,
    int M, int N, int Keff)
{
    const __nv_bfloat16* A = (const __nv_bfloat16*)Av;
    const __nv_bfloat16* B = (const __nv_bfloat16*)Bv;
    extern __shared__ char smem[];
    const uint32_t sb = smem_u32(smem);
    const int tid = threadIdx.x;
    const int bm = blockIdx.y * BM, bn = blockIdx.x * BN;
    const int w = tid >> 5, lane = tid & 31;
    const int wm = w & 1, wn = w >> 1;       // warp grid 2(m) x 4(n), 64x32 tiles

    float acc[4][4][4];
    #pragma unroll
    for (int i = 0; i < 4; i++)
        #pragma unroll
        for (int j = 0; j < 4; j++)
            #pragma unroll
            for (int t = 0; t < 4; t++) acc[i][j][t] = 0.f;

    const int KC = Keff / BKC;

    auto load_stage = [&](int st, int c) {
        const uint32_t s0 = sb + st * STAGE_SB;
        const int k0 = c * BKC;
        #pragma unroll
        for (int i = 0; i < 4; i++) {               // A: 1024 16B chunks
            const int idx = tid + i * 256;
            const int r = idx >> 3, ch = idx & 7;
            cp16(s0 + r * PITCHB + ch * 16,
                 A + (size_t)(bm + r) * Keff + k0 + ch * 8);
        }
        #pragma unroll
        for (int i = 0; i < 4; i++) {               // B: 1024 16B chunks
            const int idx = tid + i * 256;
            const int r = idx >> 3, ch = idx & 7;
            cp16(s0 + TILE_SB + r * PITCHB + ch * 16,
                 B + (size_t)(bn + r) * Keff + k0 + ch * 8);
        }
        asm volatile("cp.async.commit_group;" ::: "memory");
    };

    load_stage(0, 0);
    load_stage(1, 1);

    for (int c = 0; c < KC; c++) {
        const int st = c % NSTAGE;
        asm volatile("cp.async.wait_group 1;" ::: "memory");
        __syncthreads();

        if (c + 2 < KC) load_stage((c + 2) % NSTAGE, c + 2);
        else asm volatile("cp.async.commit_group;" ::: "memory");

        const uint32_t sA = sb + st * STAGE_SB;
        const uint32_t sB = sA + TILE_SB;

        #pragma unroll
        for (int ks = 0; ks < 4; ks++) {
            const int kc = ks * 16;
            uint32_t afr[4][4], bfr[4][2];
            #pragma unroll
            for (int mt = 0; mt < 4; mt++) {
                const int row = wm * 64 + mt * 16 + (lane & 15);
                const int col = kc + (lane >> 4) * 8;
                ldm4(afr[mt], sA + row * PITCHB + col * 2);
            }
            #pragma unroll
            for (int np = 0; np < 2; np++) {
                const int n = wn * 32 + np * 16 + ((lane >> 4) & 1) * 8 + (lane & 7);
                const int col = kc + ((lane >> 3) & 1) * 8;
                uint32_t r[4];
                ldm4(r, sB + n * PITCHB + col * 2);
                bfr[2 * np][0] = r[0]; bfr[2 * np][1] = r[1];
                bfr[2 * np + 1][0] = r[2]; bfr[2 * np + 1][1] = r[3];
            }
            #pragma unroll
            for (int mt = 0; mt < 4; mt++)
                #pragma unroll
                for (int nt = 0; nt < 4; nt++) {
                    if (FP16) mma_f16(acc[mt][nt], afr[mt], bfr[nt]);
                    else      mma_bf (acc[mt][nt], afr[mt], bfr[nt]);
                }
        }
    }

    // -------- epilogue --------
    const int r0 = lane >> 2, cp2 = (lane & 3) * 2;
    #pragma unroll
    for (int mt = 0; mt < 4; mt++) {
        #pragma unroll
        for (int nt = 0; nt < 4; nt++) {
            const int col = bn + wn * 32 + nt * 8 + cp2;
            const float2 bv = *(const float2*)(bias + col);
            #pragma unroll
            for (int half_ = 0; half_ < 2; half_++) {
                const int row = bm + wm * 64 + mt * 16 + r0 + half_ * 8;
                float v0 = acc[mt][nt][2 * half_ + 0] + bv.x;
                float v1 = acc[mt][nt][2 * half_ + 1] + bv.y;
                if (EPI == 1) {
                    const float2 rv = *(const float2*)(Rres + (size_t)row * N + col);
                    v0 += rv.x; v1 += rv.y;
                }
                if (EPI == 2) {
                    v0 = 0.5f * v0 * (1.0f + erff(v0 * 0.70710678118654752f));
                    v1 = 0.5f * v1 * (1.0f + erff(v1 * 0.70710678118654752f));
                    const __half h0 = __float2half(v0);
                    const __half h1 = __float2half(v1);
                    const __half l0 = __float2half(v0 - __half2float(h0));
                    const __half l1 = __float2half(v1 - __half2float(h1));
                    const size_t o = (size_t)row * (2 * (size_t)N) + col;
                    *(__half2*)(Cp + o)     = __halves2half2(h0, h1);
                    *(__half2*)(Cp + o + N) = __halves2half2(l0, l1);
                } else {
                    *(float2*)(Cf + (size_t)row * N + col) = make_float2(v0, v1);
                }
            }
        }
    }
}

// ---------------- bf16 weight transpose + pack: W[K][N] -> T[N][3K] ----
// T = [hi | hi | lo]
__global__ __launch_bounds__(256) void transpose_pack(
    const float* __restrict__ W, __nv_bfloat16* __restrict__ T, int K, int N)
{
    __shared__ float t[32][33];
    const int n0 = blockIdx.x * 32, k0 = blockIdx.y * 32;
    const int tx = threadIdx.x & 31, ty = threadIdx.x >> 5;  // 32 x 8
    #pragma unroll
    for (int i = 0; i < 32; i += 8)
        t[ty + i][tx] = W[(size_t)(k0 + ty + i) * N + n0 + tx];
    __syncthreads();
    #pragma unroll
    for (int i = 0; i < 32; i += 8) {
        const float v = t[tx][ty + i];
        const __nv_bfloat16 h = __float2bfloat16(v);
        const __nv_bfloat16 l = __float2bfloat16(v - __bfloat162float(h));
        const size_t o = (size_t)(n0 + ty + i) * (3 * (size_t)K) + k0 + tx;
        T[o]         = h;
        T[o + K]     = h;
        T[o + 2 * K] = l;
    }
}

// ---------------- fp16 weight transpose + pack: W[K][N] -> T[N][2K] ----
// T = [hi | hi]  (duplicated; activations carry the lo split)
__global__ __launch_bounds__(256) void transpose_pack_f16(
    const float* __restrict__ W, __half* __restrict__ T, int K, int N)
{
    __shared__ float t[32][33];
    const int n0 = blockIdx.x * 32, k0 = blockIdx.y * 32;
    const int tx = threadIdx.x & 31, ty = threadIdx.x >> 5;  // 32 x 8
    #pragma unroll
    for (int i = 0; i < 32; i += 8)
        t[ty + i][tx] = W[(size_t)(k0 + ty + i) * N + n0 + tx];
    __syncthreads();
    #pragma unroll
    for (int i = 0; i < 32; i += 8) {
        const __half h = __float2half(t[tx][ty + i]);
        const size_t o = (size_t)(n0 + ty + i) * (2 * (size_t)K) + k0 + tx;
        T[o]     = h;
        T[o + K] = h;
    }
}

// ---------------- LayerNorm -> bf16 3-seg [hi|lo|hi] -------------------
__global__ __launch_bounds__(256) void ln_pack_kernel(
    const float* __restrict__ X, const float* __restrict__ w,
    const float* __restrict__ b, __nv_bfloat16* __restrict__ Yp)
{
    const int row = blockIdx.x;
    const int tid = threadIdx.x;
    const float* x = X + (size_t)row * DD;

    float4 xv = *(const float4*)(x + tid * 4);
    float s  = xv.x + xv.y + xv.z + xv.w;
    float s2 = fmaf(xv.x, xv.x, fmaf(xv.y, xv.y, fmaf(xv.z, xv.z, xv.w * xv.w)));
    #pragma unroll
    for (int o = 16; o; o >>= 1) {
        s  += __shfl_xor_sync(0xFFFFFFFFu, s,  o);
        s2 += __shfl_xor_sync(0xFFFFFFFFu, s2, o);
    }
    __shared__ float sh[8], sh2[8];
    const int lane = tid & 31, wid = tid >> 5;
    if (lane == 0) { sh[wid] = s; sh2[wid] = s2; }
    __syncthreads();
    float S = 0.f, S2 = 0.f;
    #pragma unroll
    for (int i = 0; i < 8; i++) { S += sh[i]; S2 += sh2[i]; }
    const float mean = S * (1.0f / DD);
    const float var  = S2 * (1.0f / DD) - mean * mean;
    const float inv  = rsqrtf(var + 1e-5f);

    float4 wv = *(const float4*)(w + tid * 4);
    float4 bv = *(const float4*)(b + tid * 4);
    float y[4];
    y[0] = (xv.x - mean) * inv * wv.x + bv.x;
    y[1] = (xv.y - mean) * inv * wv.y + bv.y;
    y[2] = (xv.z - mean) * inv * wv.z + bv.z;
    y[3] = (xv.w - mean) * inv * wv.w + bv.w;

    __nv_bfloat16 h[4], l[4];
    #pragma unroll
    for (int t = 0; t < 4; t++) {
        h[t] = __float2bfloat16(y[t]);
        l[t] = __float2bfloat16(y[t] - __bfloat162float(h[t]));
    }
    const size_t o = (size_t)row * K3D + tid * 4;
    *(__nv_bfloat162*)(Yp + o)              = __nv_bfloat162(h[0], h[1]);
    *(__nv_bfloat162*)(Yp + o + 2)          = __nv_bfloat162(h[2], h[3]);
    *(__nv_bfloat162*)(Yp + o + DD)         = __nv_bfloat162(l[0], l[1]);
    *(__nv_bfloat162*)(Yp + o + DD + 2)     = __nv_bfloat162(l[2], l[3]);
    *(__nv_bfloat162*)(Yp + o + 2 * DD)     = __nv_bfloat162(h[0], h[1]);
    *(__nv_bfloat162*)(Yp + o + 2 * DD + 2) = __nv_bfloat162(h[2], h[3]);
}

// ---------------- LayerNorm -> fp16 2-seg [hi|lo] ----------------------
__global__ __launch_bounds__(256) void ln_pack_f16_kernel(
    const float* __restrict__ X, const float* __restrict__ w,
    const float* __restrict__ b, __half* __restrict__ Yp)
{
    const int row = blockIdx.x;
    const int tid = threadIdx.x;
    const float* x = X + (size_t)row * DD;

    float4 xv = *(const float4*)(x + tid * 4);
    float s  = xv.x + xv.y + xv.z + xv.w;
    float s2 = fmaf(xv.x, xv.x, fmaf(xv.y, xv.y, fmaf(xv.z, xv.z, xv.w * xv.w)));
    #pragma unroll
    for (int o = 16; o; o >>= 1) {
        s  += __shfl_xor_sync(0xFFFFFFFFu, s,  o);
        s2 += __shfl_xor_sync(0xFFFFFFFFu, s2, o);
    }
    __shared__ float sh[8], sh2[8];
    const int lane = tid & 31, wid = tid >> 5;
    if (lane == 0) { sh[wid] = s; sh2[wid] = s2; }
    __syncthreads();
    float S = 0.f, S2 = 0.f;
    #pragma unroll
    for (int i = 0; i < 8; i++) { S += sh[i]; S2 += sh2[i]; }
    const float mean = S * (1.0f / DD);
    const float var  = S2 * (1.0f / DD) - mean * mean;
    const float inv  = rsqrtf(var + 1e-5f);

    float4 wv = *(const float4*)(w + tid * 4);
    float4 bv = *(const float4*)(b + tid * 4);
    float y[4];
    y[0] = (xv.x - mean) * inv * wv.x + bv.x;
    y[1] = (xv.y - mean) * inv * wv.y + bv.y;
    y[2] = (xv.z - mean) * inv * wv.z + bv.z;
    y[3] = (xv.w - mean) * inv * wv.w + bv.w;

    __half h[4], l[4];
    #pragma unroll
    for (int t = 0; t < 4; t++) {
        h[t] = __float2half(y[t]);
        l[t] = __float2half(y[t] - __half2float(h[t]));
    }
    const size_t o = (size_t)row * K2D + tid * 4;
    *(__half2*)(Yp + o)          = __halves2half2(h[0], h[1]);
    *(__half2*)(Yp + o + 2)      = __halves2half2(h[2], h[3]);
    *(__half2*)(Yp + o + DD)     = __halves2half2(l[0], l[1]);
    *(__half2*)(Yp + o + DD + 2) = __halves2half2(l[2], l[3]);
}

// ---------------- fused per-token linear attention -> bf16 3-seg -------
__device__ __forceinline__ float elu1(float x) {
    return x > 0.f ? x + 1.0f : expf(x);
}

__global__ __launch_bounds__(256) void attn_kernel(
    const float* __restrict__ Q, const float* __restrict__ K_,
    const float* __restrict__ V, __nv_bfloat16* __restrict__ Op)
{
    __shared__ float fq[HH][HD];
    __shared__ float fk[HH][HD];
    __shared__ float vv[HH][HD];
    __shared__ float kv[HD][HD];
    __shared__ float ksum[HD];

    const size_t base  = (size_t)blockIdx.x * DD;
    const size_t base3 = (size_t)blockIdx.x * K3D;
    const int tid = threadIdx.x;

    {
        float4 q4 = *(const float4*)(Q  + base + tid * 4);
        float4 k4 = *(const float4*)(K_ + base + tid * 4);
        float4 v4 = *(const float4*)(V  + base + tid * 4);
        float* fqf = &fq[0][0]; float* fkf = &fk[0][0]; float* vvf = &vv[0][0];
        fqf[tid*4+0] = elu1(q4.x); fqf[tid*4+1] = elu1(q4.y);
        fqf[tid*4+2] = elu1(q4.z); fqf[tid*4+3] = elu1(q4.w);
        fkf[tid*4+0] = elu1(k4.x); fkf[tid*4+1] = elu1(k4.y);
        fkf[tid*4+2] = elu1(k4.z); fkf[tid*4+3] = elu1(k4.w);
        vvf[tid*4+0] = v4.x; vvf[tid*4+1] = v4.y;
        vvf[tid*4+2] = v4.z; vvf[tid*4+3] = v4.w;
    }
    __syncthreads();

    if (tid < HD) {
        float s = 0.f;
        #pragma unroll
        for (int h = 0; h < HH; h++) s += fk[h][tid];
        ksum[tid] = s;
    }
    {
        const int e = tid & 63;
        const int d0 = tid >> 6;
        #pragma unroll
        for (int j = 0; j < 16; j++) {
            const int d = d0 + j * 4;
            float s = 0.f;
            #pragma unroll
            for (int h = 0; h < HH; h++) s = fmaf(fk[h][d], vv[h][e], s);
            kv[d][e] = s;
        }
    }
    __syncthreads();
    {
        const int e = tid & 63;
        const int h0 = tid >> 6;
        #pragma unroll
        for (int j = 0; j < 4; j++) {
            const int h = h0 + j * 4;
            float s = 0.f, sq = 0.f;
            #pragma unroll
            for (int d = 0; d < HD; d++) {
                const float f = fq[h][d];
                s  = fmaf(f, kv[d][e], s);
                sq = fmaf(f, ksum[d], sq);
            }
            const float val = s / (sq + 1e-6f);
            const __nv_bfloat16 hi = __float2bfloat16(val);
            const __nv_bfloat16 lo = __float2bfloat16(val - __bfloat162float(hi));
            const size_t o = base3 + h * HD + e;
            Op[o]          = hi;
            Op[o + DD]     = lo;
            Op[o + 2 * DD] = hi;
        }
    }
}

// ---------------- launch ----------------
extern "C" void kernel_launch(void* const* d_in, const int* in_sizes, int n_in,
                              void* d_out, int out_size)
{
    const float* q_x    = (const float*)d_in[0];
    const float* ln1_w  = (const float*)d_in[1];
    const float* ln1_b  = (const float*)d_in[2];
    const float* wq     = (const float*)d_in[3];
    const float* bq     = (const float*)d_in[4];
    const float* wk     = (const float*)d_in[5];
    const float* bk     = (const float*)d_in[6];
    const float* wv     = (const float*)d_in[7];
    const float* bv     = (const float*)d_in[8];
    const float* wo     = (const float*)d_in[9];
    const float* bo     = (const float*)d_in[10];
    const float* ln2_w  = (const float*)d_in[11];
    const float* ln2_b  = (const float*)d_in[12];
    const float* fc_w   = (const float*)d_in[13];
    const float* fc_b   = (const float*)d_in[14];
    const float* proj_w = (const float*)d_in[15];
    const float* proj_b = (const float*)d_in[16];
    float* out = (float*)d_out;

    __nv_bfloat16 *xnp, *ap, *wqp, *wkp, *wvp, *wop;
    __half *xn2p, *hp2, *fcp2, *pjp2;
    float *q, *k, *v, *x;
    cudaGetSymbolAddress((void**)&xnp,  g_xnp);
    cudaGetSymbolAddress((void**)&ap,   g_ap);
    cudaGetSymbolAddress((void**)&xn2p, g_xn2p);
    cudaGetSymbolAddress((void**)&hp2,  g_hp2);
    cudaGetSymbolAddress((void**)&q,    g_q);
    cudaGetSymbolAddress((void**)&k,    g_k);
    cudaGetSymbolAddress((void**)&v,    g_v);
    cudaGetSymbolAddress((void**)&x,    g_x);
    cudaGetSymbolAddress((void**)&wqp,  g_wqp);
    cudaGetSymbolAddress((void**)&wkp,  g_wkp);
    cudaGetSymbolAddress((void**)&wvp,  g_wvp);
    cudaGetSymbolAddress((void**)&wop,  g_wop);
    cudaGetSymbolAddress((void**)&fcp2, g_fcp2);
    cudaGetSymbolAddress((void**)&pjp2, g_pjp2);

    cudaFuncSetAttribute((const void*)mma_gemm<0,0>, cudaFuncAttributeMaxDynamicSharedMemorySize, SMEM_BYTES);
    cudaFuncSetAttribute((const void*)mma_gemm<1,0>, cudaFuncAttributeMaxDynamicSharedMemorySize, SMEM_BYTES);
    cudaFuncSetAttribute((const void*)mma_gemm<1,1>, cudaFuncAttributeMaxDynamicSharedMemorySize, SMEM_BYTES);
    cudaFuncSetAttribute((const void*)mma_gemm<2,1>, cudaFuncAttributeMaxDynamicSharedMemorySize, SMEM_BYTES);

    // weight prep
    transpose_pack<<<dim3(DD/32,  DD/32),  256>>>(wq, wqp, DD, DD);
    transpose_pack<<<dim3(DD/32,  DD/32),  256>>>(wk, wkp, DD, DD);
    transpose_pack<<<dim3(DD/32,  DD/32),  256>>>(wv, wvp, DD, DD);
    transpose_pack<<<dim3(DD/32,  DD/32),  256>>>(wo, wop, DD, DD);
    transpose_pack_f16<<<dim3(MLP/32, DD/32),  256>>>(fc_w,   fcp2, DD,  MLP);
    transpose_pack_f16<<<dim3(DD/32,  MLP/32), 256>>>(proj_w, pjp2, MLP, DD);

    const dim3 gD (DD  / BN, MM / BM);   // (8, 128)
    const dim3 gML(MLP / BN, MM / BM);   // (32, 128)

    // 1) xn = LN1(q_x) -> bf16 3-seg
    ln_pack_kernel<<<MM, 256>>>(q_x, ln1_w, ln1_b, xnp);
    // 2) q/k/v = xn @ w* + b*  (bf16 3-seg, fp32 out)
    mma_gemm<0,0><<<gD, 256, SMEM_BYTES>>>(xnp, wqp, bq, nullptr, q, nullptr, MM, DD, K3D);
    mma_gemm<0,0><<<gD, 256, SMEM_BYTES>>>(xnp, wkp, bk, nullptr, k, nullptr, MM, DD, K3D);
    mma_gemm<0,0><<<gD, 256, SMEM_BYTES>>>(xnp, wvp, bv, nullptr, v, nullptr, MM, DD, K3D);
    // 3) fused per-token linear attention -> bf16 3-seg
    attn_kernel<<<MM, 256>>>(q, k, v, ap);
    // 4) x = q_x + attn @ wo + bo  (bf16 3-seg, fp32 out)
    mma_gemm<1,0><<<gD, 256, SMEM_BYTES>>>(ap, wop, bo, q_x, x, nullptr, MM, DD, K3D);
    // 5) xn2 = LN2(x) -> fp16 2-seg
    ln_pack_f16_kernel<<<MM, 256>>>(x, ln2_w, ln2_b, xn2p);
    // 6) h = gelu(xn2 @ fc_w + fc_b) -> fp16 2-seg  (fp16 GEMM, K=2048)
    mma_gemm<2,1><<<gML, 256, SMEM_BYTES>>>(xn2p, fcp2, fc_b, nullptr, nullptr, hp2, MM, MLP, K2D);
    // 7) out = x + h @ proj_w + proj_b  (fp16 GEMM, K=8192)
    mma_gemm<1,1><<<gD, 256, SMEM_BYTES>>>(hp2, pjp2, proj_b, x, out, nullptr, MM, DD, K2M);
}

// round 13
// speedup vs baseline: 1.6252x; 1.1338x over previous
#include <cuda_runtime.h>
#include <cuda_fp16.h>
#include <math.h>
#include <stdint.h>

// ---------------- problem constants ----------------
#define BB 4
#define NN 4096
#define DD 1024
#define HH 16
#define HD 64
#define MLP 4096
#define MM (BB*NN)          // 16384 rows
#define K2D (2*DD)          // 2048
#define K2M (2*MLP)         // 8192

// ---------------- scratch (device globals; no allocation allowed) ------
// fp16 2-seg packed activations: [hi | lo] along K
__device__ __align__(256) __half g_xnp[(size_t)MM * K2D];
__device__ __align__(256) __half g_ap [(size_t)MM * K2D];
__device__ __align__(256) __half g_hp [(size_t)MM * K2M];
__device__ __align__(256) float g_q[(size_t)MM * DD];
__device__ __align__(256) float g_k[(size_t)MM * DD];
__device__ __align__(256) float g_v[(size_t)MM * DD];
__device__ __align__(256) float g_x[(size_t)MM * DD];
// fp16 transposed weights [N][2K]: [hi | hi] (duplicated; lo lives in A)
__device__ __align__(256) __half g_wqp[(size_t)DD * K2D];
__device__ __align__(256) __half g_wkp[(size_t)DD * K2D];
__device__ __align__(256) __half g_wvp[(size_t)DD * K2D];
__device__ __align__(256) __half g_wop[(size_t)DD * K2D];
__device__ __align__(256) __half g_fcp[(size_t)MLP * K2D];
__device__ __align__(256) __half g_pjp[(size_t)DD * K2M];

// ================= PTX helpers (compute_103-safe: sm_80+ features) =====
__device__ __forceinline__ uint32_t smem_u32(const void* p) {
    uint32_t a;
    asm("{ .reg .u64 t; cvta.to.shared.u64 t, %1; cvt.u32.u64 %0, t; }" : "=r"(a) : "l"(p));
    return a;
}
__device__ __forceinline__ void cp16(uint32_t sdst, const void* gsrc) {
    asm volatile("cp.async.cg.shared.global [%0], [%1], 16;" :: "r"(sdst), "l"(gsrc) : "memory");
}
__device__ __forceinline__ void ldm4(uint32_t* r, uint32_t a) {
    asm volatile("ldmatrix.sync.aligned.m8n8.x4.shared.b16 {%0,%1,%2,%3}, [%4];"
        : "=r"(r[0]), "=r"(r[1]), "=r"(r[2]), "=r"(r[3]) : "r"(a));
}
__device__ __forceinline__ void mma_f16(float* d, const uint32_t* a, const uint32_t* b) {
    asm volatile("mma.sync.aligned.m16n8k16.row.col.f32.f16.f16.f32 "
        "{%0,%1,%2,%3},{%4,%5,%6,%7},{%8,%9},{%0,%1,%2,%3};"
        : "+f"(d[0]), "+f"(d[1]), "+f"(d[2]), "+f"(d[3])
        : "r"(a[0]), "r"(a[1]), "r"(a[2]), "r"(a[3]), "r"(b[0]), "r"(b[1]));
}

// ================= HMMA GEMM: C[M,N] = A[M,Keff] @ B[N,Keff]^T =========
// CTA 128x128, 8 warps (2m x 4n) of 64x32, BKC=64, 3 stages, 2 CTA/SM.
// EPI: 0 = +bias (fp32), 1 = +bias+R (fp32), 2 = gelu(+bias) -> fp16 2-seg
#define BM 128
#define BN 128
#define BKC 64
#define PITCHB 144                     // bytes per smem row (128B data + 16B pad)
#define TILE_SB (128 * PITCHB)         // 18432
#define STAGE_SB (2 * TILE_SB)         // 36864
#define NSTAGE 3
#define SMEM_BYTES (NSTAGE * STAGE_SB) // 110592 per CTA; x2 CTA = 216KB/SM

template<int EPI>
__global__ __launch_bounds__(256, 2) void mma_gemm(
    const __half* __restrict__ A, const __half* __restrict__ B,
    const float* __restrict__ bias, const float* __restrict__ Rres,
    float* __restrict__ Cf, __half* __restrict__ Cp,
    int M, int N, int Keff)
{
    extern __shared__ char smem[];
    const uint32_t sb = smem_u32(smem);
    const int tid = threadIdx.x;
    const int bm = blockIdx.y * BM, bn = blockIdx.x * BN;
    const int w = tid >> 5, lane = tid & 31;
    const int wm = w & 1, wn = w >> 1;       // warp grid 2(m) x 4(n), 64x32 tiles

    float acc[4][4][4];
    #pragma unroll
    for (int i = 0; i < 4; i++)
        #pragma unroll
        for (int j = 0; j < 4; j++)
            #pragma unroll
            for (int t = 0; t < 4; t++) acc[i][j][t] = 0.f;

    const int KC = Keff / BKC;

    auto load_stage = [&](int st, int c) {
        const uint32_t s0 = sb + st * STAGE_SB;
        const int k0 = c * BKC;
        #pragma unroll
        for (int i = 0; i < 4; i++) {               // A: 1024 16B chunks
            const int idx = tid + i * 256;
            const int r = idx >> 3, ch = idx & 7;
            cp16(s0 + r * PITCHB + ch * 16,
                 A + (size_t)(bm + r) * Keff + k0 + ch * 8);
        }
        #pragma unroll
        for (int i = 0; i < 4; i++) {               // B: 1024 16B chunks
            const int idx = tid + i * 256;
            const int r = idx >> 3, ch = idx & 7;
            cp16(s0 + TILE_SB + r * PITCHB + ch * 16,
                 B + (size_t)(bn + r) * Keff + k0 + ch * 8);
        }
        asm volatile("cp.async.commit_group;" ::: "memory");
    };

    load_stage(0, 0);
    load_stage(1, 1);

    for (int c = 0; c < KC; c++) {
        const int st = c % NSTAGE;
        asm volatile("cp.async.wait_group 1;" ::: "memory");
        __syncthreads();

        if (c + 2 < KC) load_stage((c + 2) % NSTAGE, c + 2);
        else asm volatile("cp.async.commit_group;" ::: "memory");

        const uint32_t sA = sb + st * STAGE_SB;
        const uint32_t sB = sA + TILE_SB;

        #pragma unroll
        for (int ks = 0; ks < 4; ks++) {
            const int kc = ks * 16;
            uint32_t afr[4][4], bfr[4][2];
            #pragma unroll
            for (int mt = 0; mt < 4; mt++) {
                const int row = wm * 64 + mt * 16 + (lane & 15);
                const int col = kc + (lane >> 4) * 8;
                ldm4(afr[mt], sA + row * PITCHB + col * 2);
            }
            #pragma unroll
            for (int np = 0; np < 2; np++) {
                const int n = wn * 32 + np * 16 + ((lane >> 4) & 1) * 8 + (lane & 7);
                const int col = kc + ((lane >> 3) & 1) * 8;
                uint32_t r[4];
                ldm4(r, sB + n * PITCHB + col * 2);
                bfr[2 * np][0] = r[0]; bfr[2 * np][1] = r[1];
                bfr[2 * np + 1][0] = r[2]; bfr[2 * np + 1][1] = r[3];
            }
            #pragma unroll
            for (int mt = 0; mt < 4; mt++)
                #pragma unroll
                for (int nt = 0; nt < 4; nt++)
                    mma_f16(acc[mt][nt], afr[mt], bfr[nt]);
        }
    }

    // -------- epilogue --------
    const int r0 = lane >> 2, cp2 = (lane & 3) * 2;
    #pragma unroll
    for (int mt = 0; mt < 4; mt++) {
        #pragma unroll
        for (int nt = 0; nt < 4; nt++) {
            const int col = bn + wn * 32 + nt * 8 + cp2;
            const float2 bv = *(const float2*)(bias + col);
            #pragma unroll
            for (int half_ = 0; half_ < 2; half_++) {
                const int row = bm + wm * 64 + mt * 16 + r0 + half_ * 8;
                float v0 = acc[mt][nt][2 * half_ + 0] + bv.x;
                float v1 = acc[mt][nt][2 * half_ + 1] + bv.y;
                if (EPI == 1) {
                    const float2 rv = *(const float2*)(Rres + (size_t)row * N + col);
                    v0 += rv.x; v1 += rv.y;
                }
                if (EPI == 2) {
                    v0 = 0.5f * v0 * (1.0f + erff(v0 * 0.70710678118654752f));
                    v1 = 0.5f * v1 * (1.0f + erff(v1 * 0.70710678118654752f));
                    const __half h0 = __float2half(v0);
                    const __half h1 = __float2half(v1);
                    const __half l0 = __float2half(v0 - __half2float(h0));
                    const __half l1 = __float2half(v1 - __half2float(h1));
                    const size_t o = (size_t)row * (2 * (size_t)N) + col;
                    *(__half2*)(Cp + o)     = __halves2half2(h0, h1);
                    *(__half2*)(Cp + o + N) = __halves2half2(l0, l1);
                } else {
                    *(float2*)(Cf + (size_t)row * N + col) = make_float2(v0, v1);
                }
            }
        }
    }
}

// ---------------- fp16 weight transpose + pack: W[K][N] -> T[N][2K] ----
// T = [hi | hi]  (duplicated; activations carry the lo split)
__global__ __launch_bounds__(256) void transpose_pack_f16(
    const float* __restrict__ W, __half* __restrict__ T, int K, int N)
{
    __shared__ float t[32][33];
    const int n0 = blockIdx.x * 32, k0 = blockIdx.y * 32;
    const int tx = threadIdx.x & 31, ty = threadIdx.x >> 5;  // 32 x 8
    #pragma unroll
    for (int i = 0; i < 32; i += 8)
        t[ty + i][tx] = W[(size_t)(k0 + ty + i) * N + n0 + tx];
    __syncthreads();
    #pragma unroll
    for (int i = 0; i < 32; i += 8) {
        const __half h = __float2half(t[tx][ty + i]);
        const size_t o = (size_t)(n0 + ty + i) * (2 * (size_t)K) + k0 + tx;
        T[o]     = h;
        T[o + K] = h;
    }
}

// ---------------- LayerNorm -> fp16 2-seg [hi|lo] ----------------------
__global__ __launch_bounds__(256) void ln_pack_f16_kernel(
    const float* __restrict__ X, const float* __restrict__ w,
    const float* __restrict__ b, __half* __restrict__ Yp)
{
    const int row = blockIdx.x;
    const int tid = threadIdx.x;
    const float* x = X + (size_t)row * DD;

    float4 xv = *(const float4*)(x + tid * 4);
    float s  = xv.x + xv.y + xv.z + xv.w;
    float s2 = fmaf(xv.x, xv.x, fmaf(xv.y, xv.y, fmaf(xv.z, xv.z, xv.w * xv.w)));
    #pragma unroll
    for (int o = 16; o; o >>= 1) {
        s  += __shfl_xor_sync(0xFFFFFFFFu, s,  o);
        s2 += __shfl_xor_sync(0xFFFFFFFFu, s2, o);
    }
    __shared__ float sh[8], sh2[8];
    const int lane = tid & 31, wid = tid >> 5;
    if (lane == 0) { sh[wid] = s; sh2[wid] = s2; }
    __syncthreads();
    float S = 0.f, S2 = 0.f;
    #pragma unroll
    for (int i = 0; i < 8; i++) { S += sh[i]; S2 += sh2[i]; }
    const float mean = S * (1.0f / DD);
    const float var  = S2 * (1.0f / DD) - mean * mean;
    const float inv  = rsqrtf(var + 1e-5f);

    float4 wv = *(const float4*)(w + tid * 4);
    float4 bv = *(const float4*)(b + tid * 4);
    float y[4];
    y[0] = (xv.x - mean) * inv * wv.x + bv.x;
    y[1] = (xv.y - mean) * inv * wv.y + bv.y;
    y[2] = (xv.z - mean) * inv * wv.z + bv.z;
    y[3] = (xv.w - mean) * inv * wv.w + bv.w;

    __half h[4], l[4];
    #pragma unroll
    for (int t = 0; t < 4; t++) {
        h[t] = __float2half(y[t]);
        l[t] = __float2half(y[t] - __half2float(h[t]));
    }
    const size_t o = (size_t)row * K2D + tid * 4;
    *(__half2*)(Yp + o)          = __halves2half2(h[0], h[1]);
    *(__half2*)(Yp + o + 2)      = __halves2half2(h[2], h[3]);
    *(__half2*)(Yp + o + DD)     = __halves2half2(l[0], l[1]);
    *(__half2*)(Yp + o + DD + 2) = __halves2half2(l[2], l[3]);
}

// ---------------- fused per-token linear attention -> fp16 2-seg -------
__device__ __forceinline__ float elu1(float x) {
    return x > 0.f ? x + 1.0f : expf(x);
}

__global__ __launch_bounds__(256) void attn_kernel(
    const float* __restrict__ Q, const float* __restrict__ K_,
    const float* __restrict__ V, __half* __restrict__ Op)
{
    __shared__ float fq[HH][HD];
    __shared__ float fk[HH][HD];
    __shared__ float vv[HH][HD];
    __shared__ float kv[HD][HD];
    __shared__ float ksum[HD];

    const size_t base  = (size_t)blockIdx.x * DD;
    const size_t base2 = (size_t)blockIdx.x * K2D;
    const int tid = threadIdx.x;

    {
        float4 q4 = *(const float4*)(Q  + base + tid * 4);
        float4 k4 = *(const float4*)(K_ + base + tid * 4);
        float4 v4 = *(const float4*)(V  + base + tid * 4);
        float* fqf = &fq[0][0]; float* fkf = &fk[0][0]; float* vvf = &vv[0][0];
        fqf[tid*4+0] = elu1(q4.x); fqf[tid*4+1] = elu1(q4.y);
        fqf[tid*4+2] = elu1(q4.z); fqf[tid*4+3] = elu1(q4.w);
        fkf[tid*4+0] = elu1(k4.x); fkf[tid*4+1] = elu1(k4.y);
        fkf[tid*4+2] = elu1(k4.z); fkf[tid*4+3] = elu1(k4.w);
        vvf[tid*4+0] = v4.x; vvf[tid*4+1] = v4.y;
        vvf[tid*4+2] = v4.z; vvf[tid*4+3] = v4.w;
    }
    __syncthreads();

    if (tid < HD) {
        float s = 0.f;
        #pragma unroll
        for (int h = 0; h < HH; h++) s += fk[h][tid];
        ksum[tid] = s;
    }
    {
        const int e = tid & 63;
        const int d0 = tid >> 6;
        #pragma unroll
        for (int j = 0; j < 16; j++) {
            const int d = d0 + j * 4;
            float s = 0.f;
            #pragma unroll
            for (int h = 0; h < HH; h++) s = fmaf(fk[h][d], vv[h][e], s);
            kv[d][e] = s;
        }
    }
    __syncthreads();
    {
        const int e = tid & 63;
        const int h0 = tid >> 6;
        #pragma unroll
        for (int j = 0; j < 4; j++) {
            const int h = h0 + j * 4;
            float s = 0.f, sq = 0.f;
            #pragma unroll
            for (int d = 0; d < HD; d++) {
                const float f = fq[h][d];
                s  = fmaf(f, kv[d][e], s);
                sq = fmaf(f, ksum[d], sq);
            }
            const float val = s / (sq + 1e-6f);
            const __half hi = __float2half(val);
            const __half lo = __float2half(val - __half2float(hi));
            const size_t o = base2 + h * HD + e;
            Op[o]      = hi;
            Op[o + DD] = lo;
        }
    }
}

// ---------------- launch ----------------
extern "C" void kernel_launch(void* const* d_in, const int* in_sizes, int n_in,
                              void* d_out, int out_size)
{
    const float* q_x    = (const float*)d_in[0];
    const float* ln1_w  = (const float*)d_in[1];
    const float* ln1_b  = (const float*)d_in[2];
    const float* wq     = (const float*)d_in[3];
    const float* bq     = (const float*)d_in[4];
    const float* wk     = (const float*)d_in[5];
    const float* bk     = (const float*)d_in[6];
    const float* wv     = (const float*)d_in[7];
    const float* bv     = (const float*)d_in[8];
    const float* wo     = (const float*)d_in[9];
    const float* bo     = (const float*)d_in[10];
    const float* ln2_w  = (const float*)d_in[11];
    const float* ln2_b  = (const float*)d_in[12];
    const float* fc_w   = (const float*)d_in[13];
    const float* fc_b   = (const float*)d_in[14];
    const float* proj_w = (const float*)d_in[15];
    const float* proj_b = (const float*)d_in[16];
    float* out = (float*)d_out;

    __half *xnp, *ap, *hp, *wqp, *wkp, *wvp, *wop, *fcp, *pjp;
    float *q, *k, *v, *x;
    cudaGetSymbolAddress((void**)&xnp, g_xnp);
    cudaGetSymbolAddress((void**)&ap,  g_ap);
    cudaGetSymbolAddress((void**)&hp,  g_hp);
    cudaGetSymbolAddress((void**)&q,   g_q);
    cudaGetSymbolAddress((void**)&k,   g_k);
    cudaGetSymbolAddress((void**)&v,   g_v);
    cudaGetSymbolAddress((void**)&x,   g_x);
    cudaGetSymbolAddress((void**)&wqp, g_wqp);
    cudaGetSymbolAddress((void**)&wkp, g_wkp);
    cudaGetSymbolAddress((void**)&wvp, g_wvp);
    cudaGetSymbolAddress((void**)&wop, g_wop);
    cudaGetSymbolAddress((void**)&fcp, g_fcp);
    cudaGetSymbolAddress((void**)&pjp, g_pjp);

    cudaFuncSetAttribute((const void*)mma_gemm<0>, cudaFuncAttributeMaxDynamicSharedMemorySize, SMEM_BYTES);
    cudaFuncSetAttribute((const void*)mma_gemm<1>, cudaFuncAttributeMaxDynamicSharedMemorySize, SMEM_BYTES);
    cudaFuncSetAttribute((const void*)mma_gemm<2>, cudaFuncAttributeMaxDynamicSharedMemorySize, SMEM_BYTES);

    // weight prep: transpose + fp16 pack [N][2K]
    transpose_pack_f16<<<dim3(DD/32,  DD/32),  256>>>(wq,     wqp, DD,  DD);
    transpose_pack_f16<<<dim3(DD/32,  DD/32),  256>>>(wk,     wkp, DD,  DD);
    transpose_pack_f16<<<dim3(DD/32,  DD/32),  256>>>(wv,     wvp, DD,  DD);
    transpose_pack_f16<<<dim3(DD/32,  DD/32),  256>>>(wo,     wop, DD,  DD);
    transpose_pack_f16<<<dim3(MLP/32, DD/32),  256>>>(fc_w,   fcp, DD,  MLP);
    transpose_pack_f16<<<dim3(DD/32,  MLP/32), 256>>>(proj_w, pjp, MLP, DD);

    const dim3 gD (DD  / BN, MM / BM);   // (8, 128)
    const dim3 gML(MLP / BN, MM / BM);   // (32, 128)

    // 1) xn = LN1(q_x) -> fp16 2-seg
    ln_pack_f16_kernel<<<MM, 256>>>(q_x, ln1_w, ln1_b, xnp);
    // 2) q/k/v = xn @ w* + b*  (fp32 out)
    mma_gemm<0><<<gD, 256, SMEM_BYTES>>>(xnp, wqp, bq, nullptr, q, nullptr, MM, DD, K2D);
    mma_gemm<0><<<gD, 256, SMEM_BYTES>>>(xnp, wkp, bk, nullptr, k, nullptr, MM, DD, K2D);
    mma_gemm<0><<<gD, 256, SMEM_BYTES>>>(xnp, wvp, bv, nullptr, v, nullptr, MM, DD, K2D);
    // 3) fused per-token linear attention -> fp16 2-seg
    attn_kernel<<<MM, 256>>>(q, k, v, ap);
    // 4) x = q_x + attn @ wo + bo  (fp32 out)
    mma_gemm<1><<<gD, 256, SMEM_BYTES>>>(ap, wop, bo, q_x, x, nullptr, MM, DD, K2D);
    // 5) xn2 = LN2(x) -> fp16 2-seg
    ln_pack_f16_kernel<<<MM, 256>>>(x, ln2_w, ln2_b, xnp);
    // 6) h = gelu(xn2 @ fc_w + fc_b) -> fp16 2-seg
    mma_gemm<2><<<gML, 256, SMEM_BYTES>>>(xnp, fcp, fc_b, nullptr, nullptr, hp, MM, MLP, K2D);
    // 7) out = x + h @ proj_w + proj_b  (fp32 out)
    mma_gemm<1><<<gD, 256, SMEM_BYTES>>>(hp, pjp, proj_b, x, out, nullptr, MM, DD, K2M);
}

// round 14
// speedup vs baseline: 1.8856x; 1.1602x over previous
#include <cuda_runtime.h>
#include <cuda_fp16.h>
#include <math.h>
#include <stdint.h>

// ---------------- problem constants ----------------
#define BB 4
#define NN 4096
#define DD 1024
#define HH 16
#define HD 64
#define MLP 4096
#define MM (BB*NN)          // 16384 rows
#define K2D (2*DD)          // 2048
#define D3  (3*DD)          // 3072

// ---------------- scratch (device globals; no allocation allowed) ------
// fp16 2-seg packed activations: [hi | lo] along K
__device__ __align__(256) __half g_xnp[(size_t)MM * K2D];
__device__ __align__(256) __half g_ap [(size_t)MM * K2D];
// fp16 1-seg activations (fc output)
__device__ __align__(256) __half g_hp1[(size_t)MM * MLP];
__device__ __align__(256) float g_qkv[(size_t)MM * D3];   // fused q|k|v
__device__ __align__(256) float g_x  [(size_t)MM * DD];
// fp16 transposed weights
__device__ __align__(256) __half g_wqkv[(size_t)D3 * K2D];  // [3072][2K] 2-seg dup
__device__ __align__(256) __half g_wop [(size_t)DD * K2D];
__device__ __align__(256) __half g_fcp [(size_t)MLP * K2D];
__device__ __align__(256) __half g_pjp1[(size_t)DD * MLP];  // [1024][4096] 1-seg
__device__ __align__(256) float  g_bqkv[D3];

// ================= PTX helpers (compute_103-safe: sm_80+ features) =====
__device__ __forceinline__ uint32_t smem_u32(const void* p) {
    uint32_t a;
    asm("{ .reg .u64 t; cvta.to.shared.u64 t, %1; cvt.u32.u64 %0, t; }" : "=r"(a) : "l"(p));
    return a;
}
__device__ __forceinline__ void cp16(uint32_t sdst, const void* gsrc) {
    asm volatile("cp.async.cg.shared.global [%0], [%1], 16;" :: "r"(sdst), "l"(gsrc) : "memory");
}
__device__ __forceinline__ void ldm4(uint32_t* r, uint32_t a) {
    asm volatile("ldmatrix.sync.aligned.m8n8.x4.shared.b16 {%0,%1,%2,%3}, [%4];"
        : "=r"(r[0]), "=r"(r[1]), "=r"(r[2]), "=r"(r[3]) : "r"(a));
}
__device__ __forceinline__ void mma_f16(float* d, const uint32_t* a, const uint32_t* b) {
    asm volatile("mma.sync.aligned.m16n8k16.row.col.f32.f16.f16.f32 "
        "{%0,%1,%2,%3},{%4,%5,%6,%7},{%8,%9},{%0,%1,%2,%3};"
        : "+f"(d[0]), "+f"(d[1]), "+f"(d[2]), "+f"(d[3])
        : "r"(a[0]), "r"(a[1]), "r"(a[2]), "r"(a[3]), "r"(b[0]), "r"(b[1]));
}

// ================= HMMA GEMM: C[M,N] = A[M,Keff] @ B[N,Keff]^T =========
// CTA 128x128, 8 warps (2m x 4n) of 64x32, BKC=64, 3 stages, 2 CTA/SM.
// EPI: 0 = +bias (fp32), 1 = +bias+R (fp32), 2 = gelu(+bias) -> fp16 1-seg
#define BM 128
#define BN 128
#define BKC 64
#define PITCHB 144                     // bytes per smem row (128B data + 16B pad)
#define TILE_SB (128 * PITCHB)         // 18432
#define STAGE_SB (2 * TILE_SB)         // 36864
#define NSTAGE 3
#define SMEM_BYTES (NSTAGE * STAGE_SB) // 110592 per CTA; x2 CTA = 216KB/SM

template<int EPI>
__global__ __launch_bounds__(256, 2) void mma_gemm(
    const __half* __restrict__ A, const __half* __restrict__ B,
    const float* __restrict__ bias, const float* __restrict__ Rres,
    float* __restrict__ Cf, __half* __restrict__ Cp,
    int M, int N, int Keff)
{
    extern __shared__ char smem[];
    const uint32_t sb = smem_u32(smem);
    const int tid = threadIdx.x;
    const int bm = blockIdx.y * BM, bn = blockIdx.x * BN;
    const int w = tid >> 5, lane = tid & 31;
    const int wm = w & 1, wn = w >> 1;       // warp grid 2(m) x 4(n), 64x32 tiles

    float acc[4][4][4];
    #pragma unroll
    for (int i = 0; i < 4; i++)
        #pragma unroll
        for (int j = 0; j < 4; j++)
            #pragma unroll
            for (int t = 0; t < 4; t++) acc[i][j][t] = 0.f;

    const int KC = Keff / BKC;

    auto load_stage = [&](int st, int c) {
        const uint32_t s0 = sb + st * STAGE_SB;
        const int k0 = c * BKC;
        #pragma unroll
        for (int i = 0; i < 4; i++) {               // A: 1024 16B chunks
            const int idx = tid + i * 256;
            const int r = idx >> 3, ch = idx & 7;
            cp16(s0 + r * PITCHB + ch * 16,
                 A + (size_t)(bm + r) * Keff + k0 + ch * 8);
        }
        #pragma unroll
        for (int i = 0; i < 4; i++) {               // B: 1024 16B chunks
            const int idx = tid + i * 256;
            const int r = idx >> 3, ch = idx & 7;
            cp16(s0 + TILE_SB + r * PITCHB + ch * 16,
                 B + (size_t)(bn + r) * Keff + k0 + ch * 8);
        }
        asm volatile("cp.async.commit_group;" ::: "memory");
    };

    load_stage(0, 0);
    load_stage(1, 1);

    for (int c = 0; c < KC; c++) {
        const int st = c % NSTAGE;
        asm volatile("cp.async.wait_group 1;" ::: "memory");
        __syncthreads();

        if (c + 2 < KC) load_stage((c + 2) % NSTAGE, c + 2);
        else asm volatile("cp.async.commit_group;" ::: "memory");

        const uint32_t sA = sb + st * STAGE_SB;
        const uint32_t sB = sA + TILE_SB;

        #pragma unroll
        for (int ks = 0; ks < 4; ks++) {
            const int kc = ks * 16;
            uint32_t afr[4][4], bfr[4][2];
            #pragma unroll
            for (int mt = 0; mt < 4; mt++) {
                const int row = wm * 64 + mt * 16 + (lane & 15);
                const int col = kc + (lane >> 4) * 8;
                ldm4(afr[mt], sA + row * PITCHB + col * 2);
            }
            #pragma unroll
            for (int np = 0; np < 2; np++) {
                const int n = wn * 32 + np * 16 + ((lane >> 4) & 1) * 8 + (lane & 7);
                const int col = kc + ((lane >> 3) & 1) * 8;
                uint32_t r[4];
                ldm4(r, sB + n * PITCHB + col * 2);
                bfr[2 * np][0] = r[0]; bfr[2 * np][1] = r[1];
                bfr[2 * np + 1][0] = r[2]; bfr[2 * np + 1][1] = r[3];
            }
            #pragma unroll
            for (int mt = 0; mt < 4; mt++)
                #pragma unroll
                for (int nt = 0; nt < 4; nt++)
                    mma_f16(acc[mt][nt], afr[mt], bfr[nt]);
        }
    }

    // -------- epilogue --------
    const int r0 = lane >> 2, cp2 = (lane & 3) * 2;
    #pragma unroll
    for (int mt = 0; mt < 4; mt++) {
        #pragma unroll
        for (int nt = 0; nt < 4; nt++) {
            const int col = bn + wn * 32 + nt * 8 + cp2;
            const float2 bv = *(const float2*)(bias + col);
            #pragma unroll
            for (int half_ = 0; half_ < 2; half_++) {
                const int row = bm + wm * 64 + mt * 16 + r0 + half_ * 8;
                float v0 = acc[mt][nt][2 * half_ + 0] + bv.x;
                float v1 = acc[mt][nt][2 * half_ + 1] + bv.y;
                if (EPI == 1) {
                    const float2 rv = *(const float2*)(Rres + (size_t)row * N + col);
                    v0 += rv.x; v1 += rv.y;
                }
                if (EPI == 2) {
                    v0 = 0.5f * v0 * (1.0f + erff(v0 * 0.70710678118654752f));
                    v1 = 0.5f * v1 * (1.0f + erff(v1 * 0.70710678118654752f));
                    *(__half2*)(Cp + (size_t)row * N + col) =
                        __halves2half2(__float2half(v0), __float2half(v1));
                } else {
                    *(float2*)(Cf + (size_t)row * N + col) = make_float2(v0, v1);
                }
            }
        }
    }
}

// ---------------- fp16 weight transpose + pack: W[K][N] -> T[N][2K] ----
// T = [hi | hi]  (duplicated; activations carry the lo split)
__global__ __launch_bounds__(256) void transpose_pack_f16(
    const float* __restrict__ W, __half* __restrict__ T, int K, int N)
{
    __shared__ float t[32][33];
    const int n0 = blockIdx.x * 32, k0 = blockIdx.y * 32;
    const int tx = threadIdx.x & 31, ty = threadIdx.x >> 5;  // 32 x 8
    #pragma unroll
    for (int i = 0; i < 32; i += 8)
        t[ty + i][tx] = W[(size_t)(k0 + ty + i) * N + n0 + tx];
    __syncthreads();
    #pragma unroll
    for (int i = 0; i < 32; i += 8) {
        const __half h = __float2half(t[tx][ty + i]);
        const size_t o = (size_t)(n0 + ty + i) * (2 * (size_t)K) + k0 + tx;
        T[o]     = h;
        T[o + K] = h;
    }
}

// ---------------- fp16 weight transpose 1-seg: W[K][N] -> T[N][K] ------
__global__ __launch_bounds__(256) void transpose_f16_1seg(
    const float* __restrict__ W, __half* __restrict__ T, int K, int N)
{
    __shared__ float t[32][33];
    const int n0 = blockIdx.x * 32, k0 = blockIdx.y * 32;
    const int tx = threadIdx.x & 31, ty = threadIdx.x >> 5;  // 32 x 8
    #pragma unroll
    for (int i = 0; i < 32; i += 8)
        t[ty + i][tx] = W[(size_t)(k0 + ty + i) * N + n0 + tx];
    __syncthreads();
    #pragma unroll
    for (int i = 0; i < 32; i += 8)
        T[(size_t)(n0 + ty + i) * K + k0 + tx] = __float2half(t[tx][ty + i]);
}

// ---------------- LayerNorm -> fp16 2-seg [hi|lo] ----------------------
__global__ __launch_bounds__(256) void ln_pack_f16_kernel(
    const float* __restrict__ X, const float* __restrict__ w,
    const float* __restrict__ b, __half* __restrict__ Yp)
{
    const int row = blockIdx.x;
    const int tid = threadIdx.x;
    const float* x = X + (size_t)row * DD;

    float4 xv = *(const float4*)(x + tid * 4);
    float s  = xv.x + xv.y + xv.z + xv.w;
    float s2 = fmaf(xv.x, xv.x, fmaf(xv.y, xv.y, fmaf(xv.z, xv.z, xv.w * xv.w)));
    #pragma unroll
    for (int o = 16; o; o >>= 1) {
        s  += __shfl_xor_sync(0xFFFFFFFFu, s,  o);
        s2 += __shfl_xor_sync(0xFFFFFFFFu, s2, o);
    }
    __shared__ float sh[8], sh2[8];
    const int lane = tid & 31, wid = tid >> 5;
    if (lane == 0) { sh[wid] = s; sh2[wid] = s2; }
    __syncthreads();
    float S = 0.f, S2 = 0.f;
    #pragma unroll
    for (int i = 0; i < 8; i++) { S += sh[i]; S2 += sh2[i]; }
    const float mean = S * (1.0f / DD);
    const float var  = S2 * (1.0f / DD) - mean * mean;
    const float inv  = rsqrtf(var + 1e-5f);

    float4 wv = *(const float4*)(w + tid * 4);
    float4 bv = *(const float4*)(b + tid * 4);
    float y[4];
    y[0] = (xv.x - mean) * inv * wv.x + bv.x;
    y[1] = (xv.y - mean) * inv * wv.y + bv.y;
    y[2] = (xv.z - mean) * inv * wv.z + bv.z;
    y[3] = (xv.w - mean) * inv * wv.w + bv.w;

    __half h[4], l[4];
    #pragma unroll
    for (int t = 0; t < 4; t++) {
        h[t] = __float2half(y[t]);
        l[t] = __float2half(y[t] - __half2float(h[t]));
    }
    const size_t o = (size_t)row * K2D + tid * 4;
    *(__half2*)(Yp + o)          = __halves2half2(h[0], h[1]);
    *(__half2*)(Yp + o + 2)      = __halves2half2(h[2], h[3]);
    *(__half2*)(Yp + o + DD)     = __halves2half2(l[0], l[1]);
    *(__half2*)(Yp + o + DD + 2) = __halves2half2(l[2], l[3]);
}

// ---------------- fused per-token linear attention -> fp16 2-seg -------
// reads fused QKV [MM][3072]
__device__ __forceinline__ float elu1(float x) {
    return x > 0.f ? x + 1.0f : expf(x);
}

__global__ __launch_bounds__(256) void attn_kernel(
    const float* __restrict__ QKV, __half* __restrict__ Op)
{
    __shared__ float fq[HH][HD];
    __shared__ float fk[HH][HD];
    __shared__ float vv[HH][HD];
    __shared__ float kv[HD][HD];
    __shared__ float ksum[HD];

    const size_t base  = (size_t)blockIdx.x * D3;
    const size_t base2 = (size_t)blockIdx.x * K2D;
    const int tid = threadIdx.x;

    {
        float4 q4 = *(const float4*)(QKV + base + tid * 4);
        float4 k4 = *(const float4*)(QKV + base + DD + tid * 4);
        float4 v4 = *(const float4*)(QKV + base + 2 * DD + tid * 4);
        float* fqf = &fq[0][0]; float* fkf = &fk[0][0]; float* vvf = &vv[0][0];
        fqf[tid*4+0] = elu1(q4.x); fqf[tid*4+1] = elu1(q4.y);
        fqf[tid*4+2] = elu1(q4.z); fqf[tid*4+3] = elu1(q4.w);
        fkf[tid*4+0] = elu1(k4.x); fkf[tid*4+1] = elu1(k4.y);
        fkf[tid*4+2] = elu1(k4.z); fkf[tid*4+3] = elu1(k4.w);
        vvf[tid*4+0] = v4.x; vvf[tid*4+1] = v4.y;
        vvf[tid*4+2] = v4.z; vvf[tid*4+3] = v4.w;
    }
    __syncthreads();

    if (tid < HD) {
        float s = 0.f;
        #pragma unroll
        for (int h = 0; h < HH; h++) s += fk[h][tid];
        ksum[tid] = s;
    }
    {
        const int e = tid & 63;
        const int d0 = tid >> 6;
        #pragma unroll
        for (int j = 0; j < 16; j++) {
            const int d = d0 + j * 4;
            float s = 0.f;
            #pragma unroll
            for (int h = 0; h < HH; h++) s = fmaf(fk[h][d], vv[h][e], s);
            kv[d][e] = s;
        }
    }
    __syncthreads();
    {
        const int e = tid & 63;
        const int h0 = tid >> 6;
        #pragma unroll
        for (int j = 0; j < 4; j++) {
            const int h = h0 + j * 4;
            float s = 0.f, sq = 0.f;
            #pragma unroll
            for (int d = 0; d < HD; d++) {
                const float f = fq[h][d];
                s  = fmaf(f, kv[d][e], s);
                sq = fmaf(f, ksum[d], sq);
            }
            const float val = s / (sq + 1e-6f);
            const __half hi = __float2half(val);
            const __half lo = __float2half(val - __half2float(hi));
            const size_t o = base2 + h * HD + e;
            Op[o]      = hi;
            Op[o + DD] = lo;
        }
    }
}

// ---------------- launch ----------------
extern "C" void kernel_launch(void* const* d_in, const int* in_sizes, int n_in,
                              void* d_out, int out_size)
{
    const float* q_x    = (const float*)d_in[0];
    const float* ln1_w  = (const float*)d_in[1];
    const float* ln1_b  = (const float*)d_in[2];
    const float* wq     = (const float*)d_in[3];
    const float* bq     = (const float*)d_in[4];
    const float* wk     = (const float*)d_in[5];
    const float* bk     = (const float*)d_in[6];
    const float* wv     = (const float*)d_in[7];
    const float* bv     = (const float*)d_in[8];
    const float* wo     = (const float*)d_in[9];
    const float* bo     = (const float*)d_in[10];
    const float* ln2_w  = (const float*)d_in[11];
    const float* ln2_b  = (const float*)d_in[12];
    const float* fc_w   = (const float*)d_in[13];
    const float* fc_b   = (const float*)d_in[14];
    const float* proj_w = (const float*)d_in[15];
    const float* proj_b = (const float*)d_in[16];
    float* out = (float*)d_out;

    __half *xnp, *ap, *hp1, *wqkvp, *wop, *fcp, *pjp1;
    float *qkv, *x, *bqkv;
    cudaGetSymbolAddress((void**)&xnp,   g_xnp);
    cudaGetSymbolAddress((void**)&ap,    g_ap);
    cudaGetSymbolAddress((void**)&hp1,   g_hp1);
    cudaGetSymbolAddress((void**)&qkv,   g_qkv);
    cudaGetSymbolAddress((void**)&x,     g_x);
    cudaGetSymbolAddress((void**)&wqkvp, g_wqkv);
    cudaGetSymbolAddress((void**)&wop,   g_wop);
    cudaGetSymbolAddress((void**)&fcp,   g_fcp);
    cudaGetSymbolAddress((void**)&pjp1,  g_pjp1);
    cudaGetSymbolAddress((void**)&bqkv,  g_bqkv);

    cudaFuncSetAttribute((const void*)mma_gemm<0>, cudaFuncAttributeMaxDynamicSharedMemorySize, SMEM_BYTES);
    cudaFuncSetAttribute((const void*)mma_gemm<1>, cudaFuncAttributeMaxDynamicSharedMemorySize, SMEM_BYTES);
    cudaFuncSetAttribute((const void*)mma_gemm<2>, cudaFuncAttributeMaxDynamicSharedMemorySize, SMEM_BYTES);

    // weight prep: fused QKV [3072][2K], wo/fc [N][2K], proj 1-seg [1024][4096]
    transpose_pack_f16<<<dim3(DD/32,  DD/32),  256>>>(wq, wqkvp,                       DD, DD);
    transpose_pack_f16<<<dim3(DD/32,  DD/32),  256>>>(wk, wqkvp + (size_t)DD * K2D,    DD, DD);
    transpose_pack_f16<<<dim3(DD/32,  DD/32),  256>>>(wv, wqkvp + (size_t)2*DD * K2D,  DD, DD);
    transpose_pack_f16<<<dim3(DD/32,  DD/32),  256>>>(wo, wop, DD, DD);
    transpose_pack_f16<<<dim3(MLP/32, DD/32),  256>>>(fc_w, fcp, DD, MLP);
    transpose_f16_1seg<<<dim3(DD/32,  MLP/32), 256>>>(proj_w, pjp1, MLP, DD);
    // bias concat (async D2D, graph-capturable)
    cudaMemcpyAsync(bqkv,          bq, DD * sizeof(float), cudaMemcpyDeviceToDevice);
    cudaMemcpyAsync(bqkv + DD,     bk, DD * sizeof(float), cudaMemcpyDeviceToDevice);
    cudaMemcpyAsync(bqkv + 2*DD,   bv, DD * sizeof(float), cudaMemcpyDeviceToDevice);

    const dim3 gQKV(D3  / BN, MM / BM);  // (24, 128)
    const dim3 gD  (DD  / BN, MM / BM);  // (8, 128)
    const dim3 gML (MLP / BN, MM / BM);  // (32, 128)

    // 1) xn = LN1(q_x) -> fp16 2-seg
    ln_pack_f16_kernel<<<MM, 256>>>(q_x, ln1_w, ln1_b, xnp);
    // 2) qkv = xn @ [wq|wk|wv] + [bq|bk|bv]  (fused, fp32 out)
    mma_gemm<0><<<gQKV, 256, SMEM_BYTES>>>(xnp, wqkvp, bqkv, nullptr, qkv, nullptr, MM, D3, K2D);
    // 3) fused per-token linear attention -> fp16 2-seg
    attn_kernel<<<MM, 256>>>(qkv, ap);
    // 4) x = q_x + attn @ wo + bo  (fp32 out)
    mma_gemm<1><<<gD, 256, SMEM_BYTES>>>(ap, wop, bo, q_x, x, nullptr, MM, DD, K2D);
    // 5) xn2 = LN2(x) -> fp16 2-seg
    ln_pack_f16_kernel<<<MM, 256>>>(x, ln2_w, ln2_b, xnp);
    // 6) h = gelu(xn2 @ fc_w + fc_b) -> fp16 1-seg
    mma_gemm<2><<<gML, 256, SMEM_BYTES>>>(xnp, fcp, fc_b, nullptr, nullptr, hp1, MM, MLP, K2D);
    // 7) out = x + h @ proj_w + proj_b  (1-seg fp16 GEMM, K=4096)
    mma_gemm<1><<<gD, 256, SMEM_BYTES>>>(hp1, pjp1, proj_b, x, out, nullptr, MM, DD, MLP);
}

// round 15
// speedup vs baseline: 2.6642x; 1.4130x over previous
#include <cuda_runtime.h>
#include <cuda_fp16.h>
#include <math.h>
#include <stdint.h>

// ---------------- problem constants ----------------
#define BB 4
#define NN 4096
#define DD 1024
#define HH 16
#define HD 64
#define MLP 4096
#define MM (BB*NN)          // 16384 rows
#define D3  (3*DD)          // 3072

// ---------------- scratch (device globals; no allocation allowed) ------
// fp16 1-seg activations
__device__ __align__(256) __half g_xnp[(size_t)MM * DD];
__device__ __align__(256) __half g_ap [(size_t)MM * DD];
__device__ __align__(256) __half g_hp1[(size_t)MM * MLP];
__device__ __align__(256) float g_qkv[(size_t)MM * D3];   // fused q|k|v
__device__ __align__(256) float g_x  [(size_t)MM * DD];
// fp16 transposed weights [N][K], 1-seg
__device__ __align__(256) __half g_wqkv[(size_t)D3 * DD];
__device__ __align__(256) __half g_wop [(size_t)DD * DD];
__device__ __align__(256) __half g_fcp [(size_t)MLP * DD];
__device__ __align__(256) __half g_pjp1[(size_t)DD * MLP];
__device__ __align__(256) float  g_bqkv[D3];

// ================= PTX helpers (compute_103-safe: sm_80+ features) =====
__device__ __forceinline__ uint32_t smem_u32(const void* p) {
    uint32_t a;
    asm("{ .reg .u64 t; cvta.to.shared.u64 t, %1; cvt.u32.u64 %0, t; }" : "=r"(a) : "l"(p));
    return a;
}
__device__ __forceinline__ void cp16(uint32_t sdst, const void* gsrc) {
    asm volatile("cp.async.cg.shared.global [%0], [%1], 16;" :: "r"(sdst), "l"(gsrc) : "memory");
}
__device__ __forceinline__ void ldm4(uint32_t* r, uint32_t a) {
    asm volatile("ldmatrix.sync.aligned.m8n8.x4.shared.b16 {%0,%1,%2,%3}, [%4];"
        : "=r"(r[0]), "=r"(r[1]), "=r"(r[2]), "=r"(r[3]) : "r"(a));
}
__device__ __forceinline__ void mma_f16(float* d, const uint32_t* a, const uint32_t* b) {
    asm volatile("mma.sync.aligned.m16n8k16.row.col.f32.f16.f16.f32 "
        "{%0,%1,%2,%3},{%4,%5,%6,%7},{%8,%9},{%0,%1,%2,%3};"
        : "+f"(d[0]), "+f"(d[1]), "+f"(d[2]), "+f"(d[3])
        : "r"(a[0]), "r"(a[1]), "r"(a[2]), "r"(a[3]), "r"(b[0]), "r"(b[1]));
}

// ================= HMMA GEMM: C[M,N] = A[M,K] @ B[N,K]^T ===============
// CTA 128x128, 8 warps (2m x 4n) of 64x32, BKC=64, 3 stages, 2 CTA/SM.
// EPI: 0 = +bias (fp32), 1 = +bias+R (fp32), 2 = gelu(+bias) -> fp16
#define BM 128
#define BN 128
#define BKC 64
#define PITCHB 144                     // bytes per smem row (128B data + 16B pad)
#define TILE_SB (128 * PITCHB)         // 18432
#define STAGE_SB (2 * TILE_SB)         // 36864
#define NSTAGE 3
#define SMEM_BYTES (NSTAGE * STAGE_SB) // 110592 per CTA; x2 CTA = 216KB/SM

template<int EPI>
__global__ __launch_bounds__(256, 2) void mma_gemm(
    const __half* __restrict__ A, const __half* __restrict__ B,
    const float* __restrict__ bias, const float* __restrict__ Rres,
    float* __restrict__ Cf, __half* __restrict__ Cp,
    int M, int N, int Keff)
{
    extern __shared__ char smem[];
    const uint32_t sb = smem_u32(smem);
    const int tid = threadIdx.x;
    const int bm = blockIdx.y * BM, bn = blockIdx.x * BN;
    const int w = tid >> 5, lane = tid & 31;
    const int wm = w & 1, wn = w >> 1;       // warp grid 2(m) x 4(n), 64x32 tiles

    float acc[4][4][4];
    #pragma unroll
    for (int i = 0; i < 4; i++)
        #pragma unroll
        for (int j = 0; j < 4; j++)
            #pragma unroll
            for (int t = 0; t < 4; t++) acc[i][j][t] = 0.f;

    const int KC = Keff / BKC;

    auto load_stage = [&](int st, int c) {
        const uint32_t s0 = sb + st * STAGE_SB;
        const int k0 = c * BKC;
        #pragma unroll
        for (int i = 0; i < 4; i++) {               // A: 1024 16B chunks
            const int idx = tid + i * 256;
            const int r = idx >> 3, ch = idx & 7;
            cp16(s0 + r * PITCHB + ch * 16,
                 A + (size_t)(bm + r) * Keff + k0 + ch * 8);
        }
        #pragma unroll
        for (int i = 0; i < 4; i++) {               // B: 1024 16B chunks
            const int idx = tid + i * 256;
            const int r = idx >> 3, ch = idx & 7;
            cp16(s0 + TILE_SB + r * PITCHB + ch * 16,
                 B + (size_t)(bn + r) * Keff + k0 + ch * 8);
        }
        asm volatile("cp.async.commit_group;" ::: "memory");
    };

    load_stage(0, 0);
    load_stage(1, 1);

    for (int c = 0; c < KC; c++) {
        const int st = c % NSTAGE;
        asm volatile("cp.async.wait_group 1;" ::: "memory");
        __syncthreads();

        if (c + 2 < KC) load_stage((c + 2) % NSTAGE, c + 2);
        else asm volatile("cp.async.commit_group;" ::: "memory");

        const uint32_t sA = sb + st * STAGE_SB;
        const uint32_t sB = sA + TILE_SB;

        #pragma unroll
        for (int ks = 0; ks < 4; ks++) {
            const int kc = ks * 16;
            uint32_t afr[4][4], bfr[4][2];
            #pragma unroll
            for (int mt = 0; mt < 4; mt++) {
                const int row = wm * 64 + mt * 16 + (lane & 15);
                const int col = kc + (lane >> 4) * 8;
                ldm4(afr[mt], sA + row * PITCHB + col * 2);
            }
            #pragma unroll
            for (int np = 0; np < 2; np++) {
                const int n = wn * 32 + np * 16 + ((lane >> 4) & 1) * 8 + (lane & 7);
                const int col = kc + ((lane >> 3) & 1) * 8;
                uint32_t r[4];
                ldm4(r, sB + n * PITCHB + col * 2);
                bfr[2 * np][0] = r[0]; bfr[2 * np][1] = r[1];
                bfr[2 * np + 1][0] = r[2]; bfr[2 * np + 1][1] = r[3];
            }
            #pragma unroll
            for (int mt = 0; mt < 4; mt++)
                #pragma unroll
                for (int nt = 0; nt < 4; nt++)
                    mma_f16(acc[mt][nt], afr[mt], bfr[nt]);
        }
    }

    // -------- epilogue --------
    const int r0 = lane >> 2, cp2 = (lane & 3) * 2;
    #pragma unroll
    for (int mt = 0; mt < 4; mt++) {
        #pragma unroll
        for (int nt = 0; nt < 4; nt++) {
            const int col = bn + wn * 32 + nt * 8 + cp2;
            const float2 bv = *(const float2*)(bias + col);
            #pragma unroll
            for (int half_ = 0; half_ < 2; half_++) {
                const int row = bm + wm * 64 + mt * 16 + r0 + half_ * 8;
                float v0 = acc[mt][nt][2 * half_ + 0] + bv.x;
                float v1 = acc[mt][nt][2 * half_ + 1] + bv.y;
                if (EPI == 1) {
                    const float2 rv = *(const float2*)(Rres + (size_t)row * N + col);
                    v0 += rv.x; v1 += rv.y;
                }
                if (EPI == 2) {
                    v0 = 0.5f * v0 * (1.0f + erff(v0 * 0.70710678118654752f));
                    v1 = 0.5f * v1 * (1.0f + erff(v1 * 0.70710678118654752f));
                    *(__half2*)(Cp + (size_t)row * N + col) =
                        __halves2half2(__float2half(v0), __float2half(v1));
                } else {
                    *(float2*)(Cf + (size_t)row * N + col) = make_float2(v0, v1);
                }
            }
        }
    }
}

// ---------------- fp16 weight transpose 1-seg: W[K][N] -> T[N][K] ------
__global__ __launch_bounds__(256) void transpose_f16_1seg(
    const float* __restrict__ W, __half* __restrict__ T, int K, int N)
{
    __shared__ float t[32][33];
    const int n0 = blockIdx.x * 32, k0 = blockIdx.y * 32;
    const int tx = threadIdx.x & 31, ty = threadIdx.x >> 5;  // 32 x 8
    #pragma unroll
    for (int i = 0; i < 32; i += 8)
        t[ty + i][tx] = W[(size_t)(k0 + ty + i) * N + n0 + tx];
    __syncthreads();
    #pragma unroll
    for (int i = 0; i < 32; i += 8)
        T[(size_t)(n0 + ty + i) * K + k0 + tx] = __float2half(t[tx][ty + i]);
}

// ---------------- LayerNorm -> fp16 1-seg ------------------------------
__global__ __launch_bounds__(256) void ln_f16_kernel(
    const float* __restrict__ X, const float* __restrict__ w,
    const float* __restrict__ b, __half* __restrict__ Y)
{
    const int row = blockIdx.x;
    const int tid = threadIdx.x;
    const float* x = X + (size_t)row * DD;

    float4 xv = *(const float4*)(x + tid * 4);
    float s  = xv.x + xv.y + xv.z + xv.w;
    float s2 = fmaf(xv.x, xv.x, fmaf(xv.y, xv.y, fmaf(xv.z, xv.z, xv.w * xv.w)));
    #pragma unroll
    for (int o = 16; o; o >>= 1) {
        s  += __shfl_xor_sync(0xFFFFFFFFu, s,  o);
        s2 += __shfl_xor_sync(0xFFFFFFFFu, s2, o);
    }
    __shared__ float sh[8], sh2[8];
    const int lane = tid & 31, wid = tid >> 5;
    if (lane == 0) { sh[wid] = s; sh2[wid] = s2; }
    __syncthreads();
    float S = 0.f, S2 = 0.f;
    #pragma unroll
    for (int i = 0; i < 8; i++) { S += sh[i]; S2 += sh2[i]; }
    const float mean = S * (1.0f / DD);
    const float var  = S2 * (1.0f / DD) - mean * mean;
    const float inv  = rsqrtf(var + 1e-5f);

    float4 wv = *(const float4*)(w + tid * 4);
    float4 bv = *(const float4*)(b + tid * 4);
    const size_t o = (size_t)row * DD + tid * 4;
    *(__half2*)(&((__half*)Y)[o]) = __halves2half2(
        __float2half((xv.x - mean) * inv * wv.x + bv.x),
        __float2half((xv.y - mean) * inv * wv.y + bv.y));
    *(__half2*)(&((__half*)Y)[o + 2]) = __halves2half2(
        __float2half((xv.z - mean) * inv * wv.z + bv.z),
        __float2half((xv.w - mean) * inv * wv.w + bv.w));
}

// ---------------- fused per-token linear attention -> fp16 1-seg -------
// reads fused QKV [MM][3072]
__device__ __forceinline__ float elu1(float x) {
    return x > 0.f ? x + 1.0f : expf(x);
}

__global__ __launch_bounds__(256) void attn_kernel(
    const float* __restrict__ QKV, __half* __restrict__ Op)
{
    __shared__ float fq[HH][HD];
    __shared__ float fk[HH][HD];
    __shared__ float vv[HH][HD];
    __shared__ float kv[HD][HD];
    __shared__ float ksum[HD];

    const size_t base  = (size_t)blockIdx.x * D3;
    const size_t baseo = (size_t)blockIdx.x * DD;
    const int tid = threadIdx.x;

    {
        float4 q4 = *(const float4*)(QKV + base + tid * 4);
        float4 k4 = *(const float4*)(QKV + base + DD + tid * 4);
        float4 v4 = *(const float4*)(QKV + base + 2 * DD + tid * 4);
        float* fqf = &fq[0][0]; float* fkf = &fk[0][0]; float* vvf = &vv[0][0];
        fqf[tid*4+0] = elu1(q4.x); fqf[tid*4+1] = elu1(q4.y);
        fqf[tid*4+2] = elu1(q4.z); fqf[tid*4+3] = elu1(q4.w);
        fkf[tid*4+0] = elu1(k4.x); fkf[tid*4+1] = elu1(k4.y);
        fkf[tid*4+2] = elu1(k4.z); fkf[tid*4+3] = elu1(k4.w);
        vvf[tid*4+0] = v4.x; vvf[tid*4+1] = v4.y;
        vvf[tid*4+2] = v4.z; vvf[tid*4+3] = v4.w;
    }
    __syncthreads();

    if (tid < HD) {
        float s = 0.f;
        #pragma unroll
        for (int h = 0; h < HH; h++) s += fk[h][tid];
        ksum[tid] = s;
    }
    {
        const int e = tid & 63;
        const int d0 = tid >> 6;
        #pragma unroll
        for (int j = 0; j < 16; j++) {
            const int d = d0 + j * 4;
            float s = 0.f;
            #pragma unroll
            for (int h = 0; h < HH; h++) s = fmaf(fk[h][d], vv[h][e], s);
            kv[d][e] = s;
        }
    }
    __syncthreads();
    {
        const int e = tid & 63;
        const int h0 = tid >> 6;
        #pragma unroll
        for (int j = 0; j < 4; j++) {
            const int h = h0 + j * 4;
            float s = 0.f, sq = 0.f;
            #pragma unroll
            for (int d = 0; d < HD; d++) {
                const float f = fq[h][d];
                s  = fmaf(f, kv[d][e], s);
                sq = fmaf(f, ksum[d], sq);
            }
            Op[baseo + h * HD + e] = __float2half(s / (sq + 1e-6f));
        }
    }
}

// ---------------- launch ----------------
extern "C" void kernel_launch(void* const* d_in, const int* in_sizes, int n_in,
                              void* d_out, int out_size)
{
    const float* q_x    = (const float*)d_in[0];
    const float* ln1_w  = (const float*)d_in[1];
    const float* ln1_b  = (const float*)d_in[2];
    const float* wq     = (const float*)d_in[3];
    const float* bq     = (const float*)d_in[4];
    const float* wk     = (const float*)d_in[5];
    const float* bk     = (const float*)d_in[6];
    const float* wv     = (const float*)d_in[7];
    const float* bv     = (const float*)d_in[8];
    const float* wo     = (const float*)d_in[9];
    const float* bo     = (const float*)d_in[10];
    const float* ln2_w  = (const float*)d_in[11];
    const float* ln2_b  = (const float*)d_in[12];
    const float* fc_w   = (const float*)d_in[13];
    const float* fc_b   = (const float*)d_in[14];
    const float* proj_w = (const float*)d_in[15];
    const float* proj_b = (const float*)d_in[16];
    float* out = (float*)d_out;

    __half *xnp, *ap, *hp1, *wqkvp, *wop, *fcp, *pjp1;
    float *qkv, *x, *bqkv;
    cudaGetSymbolAddress((void**)&xnp,   g_xnp);
    cudaGetSymbolAddress((void**)&ap,    g_ap);
    cudaGetSymbolAddress((void**)&hp1,   g_hp1);
    cudaGetSymbolAddress((void**)&qkv,   g_qkv);
    cudaGetSymbolAddress((void**)&x,     g_x);
    cudaGetSymbolAddress((void**)&wqkvp, g_wqkv);
    cudaGetSymbolAddress((void**)&wop,   g_wop);
    cudaGetSymbolAddress((void**)&fcp,   g_fcp);
    cudaGetSymbolAddress((void**)&pjp1,  g_pjp1);
    cudaGetSymbolAddress((void**)&bqkv,  g_bqkv);

    cudaFuncSetAttribute((const void*)mma_gemm<0>, cudaFuncAttributeMaxDynamicSharedMemorySize, SMEM_BYTES);
    cudaFuncSetAttribute((const void*)mma_gemm<1>, cudaFuncAttributeMaxDynamicSharedMemorySize, SMEM_BYTES);
    cudaFuncSetAttribute((const void*)mma_gemm<2>, cudaFuncAttributeMaxDynamicSharedMemorySize, SMEM_BYTES);

    // weight prep: all 1-seg [N][K]
    transpose_f16_1seg<<<dim3(DD/32,  DD/32),  256>>>(wq, wqkvp,                     DD, DD);
    transpose_f16_1seg<<<dim3(DD/32,  DD/32),  256>>>(wk, wqkvp + (size_t)DD * DD,   DD, DD);
    transpose_f16_1seg<<<dim3(DD/32,  DD/32),  256>>>(wv, wqkvp + (size_t)2*DD * DD, DD, DD);
    transpose_f16_1seg<<<dim3(DD/32,  DD/32),  256>>>(wo, wop, DD, DD);
    transpose_f16_1seg<<<dim3(MLP/32, DD/32),  256>>>(fc_w, fcp, DD, MLP);
    transpose_f16_1seg<<<dim3(DD/32,  MLP/32), 256>>>(proj_w, pjp1, MLP, DD);
    // bias concat (async D2D, graph-capturable)
    cudaMemcpyAsync(bqkv,        bq, DD * sizeof(float), cudaMemcpyDeviceToDevice);
    cudaMemcpyAsync(bqkv + DD,   bk, DD * sizeof(float), cudaMemcpyDeviceToDevice);
    cudaMemcpyAsync(bqkv + 2*DD, bv, DD * sizeof(float), cudaMemcpyDeviceToDevice);

    const dim3 gQKV(D3  / BN, MM / BM);  // (24, 128)
    const dim3 gD  (DD  / BN, MM / BM);  // (8, 128)
    const dim3 gML (MLP / BN, MM / BM);  // (32, 128)

    // 1) xn = LN1(q_x) -> fp16
    ln_f16_kernel<<<MM, 256>>>(q_x, ln1_w, ln1_b, xnp);
    // 2) qkv = xn @ [wq|wk|wv] + [bq|bk|bv]  (fused, K=1024, fp32 out)
    mma_gemm<0><<<gQKV, 256, SMEM_BYTES>>>(xnp, wqkvp, bqkv, nullptr, qkv, nullptr, MM, D3, DD);
    // 3) fused per-token linear attention -> fp16
    attn_kernel<<<MM, 256>>>(qkv, ap);
    // 4) x = q_x + attn @ wo + bo  (K=1024, fp32 out)
    mma_gemm<1><<<gD, 256, SMEM_BYTES>>>(ap, wop, bo, q_x, x, nullptr, MM, DD, DD);
    // 5) xn2 = LN2(x) -> fp16
    ln_f16_kernel<<<MM, 256>>>(x, ln2_w, ln2_b, xnp);
    // 6) h = gelu(xn2 @ fc_w + fc_b) -> fp16  (K=1024)
    mma_gemm<2><<<gML, 256, SMEM_BYTES>>>(xnp, fcp, fc_b, nullptr, nullptr, hp1, MM, MLP, DD);
    // 7) out = x + h @ proj_w + proj_b  (K=4096)
    mma_gemm<1><<<gD, 256, SMEM_BYTES>>>(hp1, pjp1, proj_b, x, out, nullptr, MM, DD, MLP);
}

// round 16
// speedup vs baseline: 2.6924x; 1.0106x over previous
#include <cuda_runtime.h>
#include <cuda_fp16.h>
#include <math.h>
#include <stdint.h>

// ---------------- problem constants ----------------
#define BB 4
#define NN 4096
#define DD 1024
#define HH 16
#define HD 64
#define MLP 4096
#define MM (BB*NN)          // 16384 rows
#define D3  (3*DD)          // 3072

// ---------------- scratch (device globals; no allocation allowed) ------
__device__ __align__(256) __half g_xnp[(size_t)MM * DD];
__device__ __align__(256) __half g_ap [(size_t)MM * DD];
__device__ __align__(256) __half g_hp1[(size_t)MM * MLP];
__device__ __align__(256) __half g_qkv[(size_t)MM * D3];   // fused q|k|v, fp16
__device__ __align__(256) float g_x  [(size_t)MM * DD];
// fp16 transposed weights [N][K]
__device__ __align__(256) __half g_wqkv[(size_t)D3 * DD];
__device__ __align__(256) __half g_wop [(size_t)DD * DD];
__device__ __align__(256) __half g_fcp [(size_t)MLP * DD];
__device__ __align__(256) __half g_pjp1[(size_t)DD * MLP];
__device__ __align__(256) float  g_bqkv[D3];

// ================= PTX helpers (compute_103-safe: sm_80+ features) =====
__device__ __forceinline__ uint32_t smem_u32(const void* p) {
    uint32_t a;
    asm("{ .reg .u64 t; cvta.to.shared.u64 t, %1; cvt.u32.u64 %0, t; }" : "=r"(a) : "l"(p));
    return a;
}
__device__ __forceinline__ void cp16(uint32_t sdst, const void* gsrc) {
    asm volatile("cp.async.cg.shared.global [%0], [%1], 16;" :: "r"(sdst), "l"(gsrc) : "memory");
}
__device__ __forceinline__ void ldm4(uint32_t* r, uint32_t a) {
    asm volatile("ldmatrix.sync.aligned.m8n8.x4.shared.b16 {%0,%1,%2,%3}, [%4];"
        : "=r"(r[0]), "=r"(r[1]), "=r"(r[2]), "=r"(r[3]) : "r"(a));
}
__device__ __forceinline__ void mma_f16(float* d, const uint32_t* a, const uint32_t* b) {
    asm volatile("mma.sync.aligned.m16n8k16.row.col.f32.f16.f16.f32 "
        "{%0,%1,%2,%3},{%4,%5,%6,%7},{%8,%9},{%0,%1,%2,%3};"
        : "+f"(d[0]), "+f"(d[1]), "+f"(d[2]), "+f"(d[3])
        : "r"(a[0]), "r"(a[1]), "r"(a[2]), "r"(a[3]), "r"(b[0]), "r"(b[1]));
}

// ================= HMMA GEMM: C[M,N] = A[M,K] @ B[N,K]^T ===============
// CTA 128x128, 8 warps (2m x 4n) of 64x32, BKC=64, 3 stages, 2 CTA/SM.
// EPI: 0 = +bias (fp32), 1 = +bias+R (fp32), 2 = gelu(+bias) -> fp16,
//      3 = +bias -> fp16
#define BM 128
#define BN 128
#define BKC 64
#define PITCHB 144                     // bytes per smem row (128B data + 16B pad)
#define TILE_SB (128 * PITCHB)         // 18432
#define STAGE_SB (2 * TILE_SB)         // 36864
#define NSTAGE 3
#define SMEM_BYTES (NSTAGE * STAGE_SB) // 110592 per CTA; x2 CTA = 216KB/SM

template<int EPI>
__global__ __launch_bounds__(256, 2) void mma_gemm(
    const __half* __restrict__ A, const __half* __restrict__ B,
    const float* __restrict__ bias, const float* __restrict__ Rres,
    float* __restrict__ Cf, __half* __restrict__ Cp,
    int M, int N, int Keff)
{
    extern __shared__ char smem[];
    const uint32_t sb = smem_u32(smem);
    const int tid = threadIdx.x;
    const int bm = blockIdx.y * BM, bn = blockIdx.x * BN;
    const int w = tid >> 5, lane = tid & 31;
    const int wm = w & 1, wn = w >> 1;       // warp grid 2(m) x 4(n), 64x32 tiles

    float acc[4][4][4];
    #pragma unroll
    for (int i = 0; i < 4; i++)
        #pragma unroll
        for (int j = 0; j < 4; j++)
            #pragma unroll
            for (int t = 0; t < 4; t++) acc[i][j][t] = 0.f;

    const int KC = Keff / BKC;

    auto load_stage = [&](int st, int c) {
        const uint32_t s0 = sb + st * STAGE_SB;
        const int k0 = c * BKC;
        #pragma unroll
        for (int i = 0; i < 4; i++) {               // A: 1024 16B chunks
            const int idx = tid + i * 256;
            const int r = idx >> 3, ch = idx & 7;
            cp16(s0 + r * PITCHB + ch * 16,
                 A + (size_t)(bm + r) * Keff + k0 + ch * 8);
        }
        #pragma unroll
        for (int i = 0; i < 4; i++) {               // B: 1024 16B chunks
            const int idx = tid + i * 256;
            const int r = idx >> 3, ch = idx & 7;
            cp16(s0 + TILE_SB + r * PITCHB + ch * 16,
                 B + (size_t)(bn + r) * Keff + k0 + ch * 8);
        }
        asm volatile("cp.async.commit_group;" ::: "memory");
    };

    load_stage(0, 0);
    load_stage(1, 1);

    for (int c = 0; c < KC; c++) {
        const int st = c % NSTAGE;
        asm volatile("cp.async.wait_group 1;" ::: "memory");
        __syncthreads();

        if (c + 2 < KC) load_stage((c + 2) % NSTAGE, c + 2);
        else asm volatile("cp.async.commit_group;" ::: "memory");

        const uint32_t sA = sb + st * STAGE_SB;
        const uint32_t sB = sA + TILE_SB;

        #pragma unroll
        for (int ks = 0; ks < 4; ks++) {
            const int kc = ks * 16;
            uint32_t afr[4][4], bfr[4][2];
            #pragma unroll
            for (int mt = 0; mt < 4; mt++) {
                const int row = wm * 64 + mt * 16 + (lane & 15);
                const int col = kc + (lane >> 4) * 8;
                ldm4(afr[mt], sA + row * PITCHB + col * 2);
            }
            #pragma unroll
            for (int np = 0; np < 2; np++) {
                const int n = wn * 32 + np * 16 + ((lane >> 4) & 1) * 8 + (lane & 7);
                const int col = kc + ((lane >> 3) & 1) * 8;
                uint32_t r[4];
                ldm4(r, sB + n * PITCHB + col * 2);
                bfr[2 * np][0] = r[0]; bfr[2 * np][1] = r[1];
                bfr[2 * np + 1][0] = r[2]; bfr[2 * np + 1][1] = r[3];
            }
            #pragma unroll
            for (int mt = 0; mt < 4; mt++)
                #pragma unroll
                for (int nt = 0; nt < 4; nt++)
                    mma_f16(acc[mt][nt], afr[mt], bfr[nt]);
        }
    }

    // -------- epilogue --------
    const int r0 = lane >> 2, cp2 = (lane & 3) * 2;
    #pragma unroll
    for (int mt = 0; mt < 4; mt++) {
        #pragma unroll
        for (int nt = 0; nt < 4; nt++) {
            const int col = bn + wn * 32 + nt * 8 + cp2;
            const float2 bv = *(const float2*)(bias + col);
            #pragma unroll
            for (int half_ = 0; half_ < 2; half_++) {
                const int row = bm + wm * 64 + mt * 16 + r0 + half_ * 8;
                float v0 = acc[mt][nt][2 * half_ + 0] + bv.x;
                float v1 = acc[mt][nt][2 * half_ + 1] + bv.y;
                if (EPI == 1) {
                    const float2 rv = *(const float2*)(Rres + (size_t)row * N + col);
                    v0 += rv.x; v1 += rv.y;
                }
                if (EPI == 2) {
                    v0 = 0.5f * v0 * (1.0f + erff(v0 * 0.70710678118654752f));
                    v1 = 0.5f * v1 * (1.0f + erff(v1 * 0.70710678118654752f));
                }
                if (EPI == 2 || EPI == 3) {
                    *(__half2*)(Cp + (size_t)row * N + col) =
                        __halves2half2(__float2half(v0), __float2half(v1));
                } else {
                    *(float2*)(Cf + (size_t)row * N + col) = make_float2(v0, v1);
                }
            }
        }
    }
}

// ---------------- fused weight prep: all transposes + bias concat ------
// blocks 0..4095: wq/wk/wv/wo (each 1024 tiles of 32x32)
// blocks 4096..8191: fc (128 n-tiles x 32 k-tiles)
// blocks 8192..12287: proj (32 n-tiles x 128 k-tiles)
// block 12288: bias concat
__global__ __launch_bounds__(256) void weight_prep(
    const float* __restrict__ wq, const float* __restrict__ wk,
    const float* __restrict__ wv, const float* __restrict__ wo,
    const float* __restrict__ fcw, const float* __restrict__ pjw,
    const float* __restrict__ bq, const float* __restrict__ bk,
    const float* __restrict__ bv,
    __half* __restrict__ wqkv, __half* __restrict__ wop,
    __half* __restrict__ fcp, __half* __restrict__ pjp,
    float* __restrict__ bqkv)
{
    const int t = blockIdx.x;
    if (t == 12288) {
        for (int i = threadIdx.x; i < DD; i += 256) {
            bqkv[i]          = bq[i];
            bqkv[DD + i]     = bk[i];
            bqkv[2 * DD + i] = bv[i];
        }
        return;
    }

    const float* W; __half* T;
    int K, N, nblk, kblk;
    if (t < 4096) {
        const int m = t >> 10, local = t & 1023;
        nblk = local & 31; kblk = local >> 5;
        K = DD; N = DD;
        W = (m == 0) ? wq : (m == 1) ? wk : (m == 2) ? wv : wo;
        T = (m == 0) ? wqkv
          : (m == 1) ? wqkv + (size_t)DD * DD
          : (m == 2) ? wqkv + (size_t)2 * DD * DD
          : wop;
    } else if (t < 8192) {
        const int local = t - 4096;
        nblk = local & 127; kblk = local >> 7;
        K = DD; N = MLP; W = fcw; T = fcp;
    } else {
        const int local = t - 8192;
        nblk = local & 31; kblk = local >> 5;
        K = MLP; N = DD; W = pjw; T = pjp;
    }

    __shared__ float tile[32][33];
    const int n0 = nblk * 32, k0 = kblk * 32;
    const int tx = threadIdx.x & 31, ty = threadIdx.x >> 5;
    #pragma unroll
    for (int i = 0; i < 32; i += 8)
        tile[ty + i][tx] = W[(size_t)(k0 + ty + i) * N + n0 + tx];
    __syncthreads();
    #pragma unroll
    for (int i = 0; i < 32; i += 8)
        T[(size_t)(n0 + ty + i) * K + k0 + tx] = __float2half(tile[tx][ty + i]);
}

// ---------------- LayerNorm -> fp16 1-seg ------------------------------
__global__ __launch_bounds__(256) void ln_f16_kernel(
    const float* __restrict__ X, const float* __restrict__ w,
    const float* __restrict__ b, __half* __restrict__ Y)
{
    const int row = blockIdx.x;
    const int tid = threadIdx.x;
    const float* x = X + (size_t)row * DD;

    float4 xv = *(const float4*)(x + tid * 4);
    float s  = xv.x + xv.y + xv.z + xv.w;
    float s2 = fmaf(xv.x, xv.x, fmaf(xv.y, xv.y, fmaf(xv.z, xv.z, xv.w * xv.w)));
    #pragma unroll
    for (int o = 16; o; o >>= 1) {
        s  += __shfl_xor_sync(0xFFFFFFFFu, s,  o);
        s2 += __shfl_xor_sync(0xFFFFFFFFu, s2, o);
    }
    __shared__ float sh[8], sh2[8];
    const int lane = tid & 31, wid = tid >> 5;
    if (lane == 0) { sh[wid] = s; sh2[wid] = s2; }
    __syncthreads();
    float S = 0.f, S2 = 0.f;
    #pragma unroll
    for (int i = 0; i < 8; i++) { S += sh[i]; S2 += sh2[i]; }
    const float mean = S * (1.0f / DD);
    const float var  = S2 * (1.0f / DD) - mean * mean;
    const float inv  = rsqrtf(var + 1e-5f);

    float4 wv = *(const float4*)(w + tid * 4);
    float4 bv = *(const float4*)(b + tid * 4);
    const size_t o = (size_t)row * DD + tid * 4;
    *(__half2*)(Y + o) = __halves2half2(
        __float2half((xv.x - mean) * inv * wv.x + bv.x),
        __float2half((xv.y - mean) * inv * wv.y + bv.y));
    *(__half2*)(Y + o + 2) = __halves2half2(
        __float2half((xv.z - mean) * inv * wv.z + bv.z),
        __float2half((xv.w - mean) * inv * wv.w + bv.w));
}

// ---------------- fused per-token linear attention (fp16 qkv) ----------
__device__ __forceinline__ float elu1(float x) {
    return x > 0.f ? x + 1.0f : expf(x);
}

__global__ __launch_bounds__(256) void attn_kernel(
    const __half* __restrict__ QKV, __half* __restrict__ Op)
{
    __shared__ float fq[HH][HD];
    __shared__ float fk[HH][HD];
    __shared__ float vv[HH][HD];
    __shared__ float kv[HD][HD];
    __shared__ float ksum[HD];

    const size_t base  = (size_t)blockIdx.x * D3;
    const size_t baseo = (size_t)blockIdx.x * DD;
    const int tid = threadIdx.x;

    {
        const __half2* q2 = (const __half2*)(QKV + base + tid * 4);
        const __half2* k2 = (const __half2*)(QKV + base + DD + tid * 4);
        const __half2* v2 = (const __half2*)(QKV + base + 2 * DD + tid * 4);
        const float2 qa = __half22float2(q2[0]), qb = __half22float2(q2[1]);
        const float2 ka = __half22float2(k2[0]), kb = __half22float2(k2[1]);
        const float2 va = __half22float2(v2[0]), vb = __half22float2(v2[1]);
        float* fqf = &fq[0][0]; float* fkf = &fk[0][0]; float* vvf = &vv[0][0];
        fqf[tid*4+0] = elu1(qa.x); fqf[tid*4+1] = elu1(qa.y);
        fqf[tid*4+2] = elu1(qb.x); fqf[tid*4+3] = elu1(qb.y);
        fkf[tid*4+0] = elu1(ka.x); fkf[tid*4+1] = elu1(ka.y);
        fkf[tid*4+2] = elu1(kb.x); fkf[tid*4+3] = elu1(kb.y);
        vvf[tid*4+0] = va.x; vvf[tid*4+1] = va.y;
        vvf[tid*4+2] = vb.x; vvf[tid*4+3] = vb.y;
    }
    __syncthreads();

    if (tid < HD) {
        float s = 0.f;
        #pragma unroll
        for (int h = 0; h < HH; h++) s += fk[h][tid];
        ksum[tid] = s;
    }
    {
        const int e = tid & 63;
        const int d0 = tid >> 6;
        #pragma unroll
        for (int j = 0; j < 16; j++) {
            const int d = d0 + j * 4;
            float s = 0.f;
            #pragma unroll
            for (int h = 0; h < HH; h++) s = fmaf(fk[h][d], vv[h][e], s);
            kv[d][e] = s;
        }
    }
    __syncthreads();
    {
        const int e = tid & 63;
        const int h0 = tid >> 6;
        #pragma unroll
        for (int j = 0; j < 4; j++) {
            const int h = h0 + j * 4;
            float s = 0.f, sq = 0.f;
            #pragma unroll
            for (int d = 0; d < HD; d++) {
                const float f = fq[h][d];
                s  = fmaf(f, kv[d][e], s);
                sq = fmaf(f, ksum[d], sq);
            }
            Op[baseo + h * HD + e] = __float2half(s / (sq + 1e-6f));
        }
    }
}

// ---------------- launch ----------------
extern "C" void kernel_launch(void* const* d_in, const int* in_sizes, int n_in,
                              void* d_out, int out_size)
{
    const float* q_x    = (const float*)d_in[0];
    const float* ln1_w  = (const float*)d_in[1];
    const float* ln1_b  = (const float*)d_in[2];
    const float* wq     = (const float*)d_in[3];
    const float* bq     = (const float*)d_in[4];
    const float* wk     = (const float*)d_in[5];
    const float* bk     = (const float*)d_in[6];
    const float* wv     = (const float*)d_in[7];
    const float* bv     = (const float*)d_in[8];
    const float* wo     = (const float*)d_in[9];
    const float* bo     = (const float*)d_in[10];
    const float* ln2_w  = (const float*)d_in[11];
    const float* ln2_b  = (const float*)d_in[12];
    const float* fc_w   = (const float*)d_in[13];
    const float* fc_b   = (const float*)d_in[14];
    const float* proj_w = (const float*)d_in[15];
    const float* proj_b = (const float*)d_in[16];
    float* out = (float*)d_out;

    __half *xnp, *ap, *hp1, *qkv, *wqkvp, *wop, *fcp, *pjp1;
    float *x, *bqkv;
    cudaGetSymbolAddress((void**)&xnp,   g_xnp);
    cudaGetSymbolAddress((void**)&ap,    g_ap);
    cudaGetSymbolAddress((void**)&hp1,   g_hp1);
    cudaGetSymbolAddress((void**)&qkv,   g_qkv);
    cudaGetSymbolAddress((void**)&x,     g_x);
    cudaGetSymbolAddress((void**)&wqkvp, g_wqkv);
    cudaGetSymbolAddress((void**)&wop,   g_wop);
    cudaGetSymbolAddress((void**)&fcp,   g_fcp);
    cudaGetSymbolAddress((void**)&pjp1,  g_pjp1);
    cudaGetSymbolAddress((void**)&bqkv,  g_bqkv);

    cudaFuncSetAttribute((const void*)mma_gemm<1>, cudaFuncAttributeMaxDynamicSharedMemorySize, SMEM_BYTES);
    cudaFuncSetAttribute((const void*)mma_gemm<2>, cudaFuncAttributeMaxDynamicSharedMemorySize, SMEM_BYTES);
    cudaFuncSetAttribute((const void*)mma_gemm<3>, cudaFuncAttributeMaxDynamicSharedMemorySize, SMEM_BYTES);

    // fused weight prep: all transposes + bias concat in one launch
    weight_prep<<<12289, 256>>>(wq, wk, wv, wo, fc_w, proj_w, bq, bk, bv,
                                wqkvp, wop, fcp, pjp1, bqkv);

    const dim3 gQKV(D3  / BN, MM / BM);  // (24, 128)
    const dim3 gD  (DD  / BN, MM / BM);  // (8, 128)
    const dim3 gML (MLP / BN, MM / BM);  // (32, 128)

    // 1) xn = LN1(q_x) -> fp16
    ln_f16_kernel<<<MM, 256>>>(q_x, ln1_w, ln1_b, xnp);
    // 2) qkv = xn @ [wq|wk|wv] + [bq|bk|bv]  (fused, fp16 out)
    mma_gemm<3><<<gQKV, 256, SMEM_BYTES>>>(xnp, wqkvp, bqkv, nullptr, nullptr, qkv, MM, D3, DD);
    // 3) fused per-token linear attention -> fp16
    attn_kernel<<<MM, 256>>>(qkv, ap);
    // 4) x = q_x + attn @ wo + bo  (fp32 out)
    mma_gemm<1><<<gD, 256, SMEM_BYTES>>>(ap, wop, bo, q_x, x, nullptr, MM, DD, DD);
    // 5) xn2 = LN2(x) -> fp16
    ln_f16_kernel<<<MM, 256>>>(x, ln2_w, ln2_b, xnp);
    // 6) h = gelu(xn2 @ fc_w + fc_b) -> fp16
    mma_gemm<2><<<gML, 256, SMEM_BYTES>>>(xnp, fcp, fc_b, nullptr, nullptr, hp1, MM, MLP, DD);
    // 7) out = x + h @ proj_w + proj_b
    mma_gemm<1><<<gD, 256, SMEM_BYTES>>>(hp1, pjp1, proj_b, x, out, nullptr, MM, DD, MLP);
}

// round 17
// speedup vs baseline: 2.7499x; 1.0213x over previous
#include <cuda_runtime.h>
#include <cuda_fp16.h>
#include <math.h>
#include <stdint.h>

// ---------------- problem constants ----------------
#define BB 4
#define NN 4096
#define DD 1024
#define HH 16
#define HD 64
#define MLP 4096
#define MM (BB*NN)          // 16384 rows
#define D3  (3*DD)          // 3072

// ---------------- scratch (device globals; no allocation allowed) ------
__device__ __align__(256) __half g_xnp[(size_t)MM * DD];
__device__ __align__(256) __half g_ap [(size_t)MM * DD];
__device__ __align__(256) __half g_hp1[(size_t)MM * MLP];
__device__ __align__(256) __half g_qkv[(size_t)MM * D3];   // fused q|k|v, fp16
__device__ __align__(256) float g_x  [(size_t)MM * DD];
// fp16 transposed weights [N][K]
__device__ __align__(256) __half g_wqkv[(size_t)D3 * DD];
__device__ __align__(256) __half g_wop [(size_t)DD * DD];
__device__ __align__(256) __half g_fcp [(size_t)MLP * DD];
__device__ __align__(256) __half g_pjp1[(size_t)DD * MLP];
__device__ __align__(256) float  g_bqkv[D3];

// ================= PTX helpers (compute_103-safe: sm_80+ features) =====
__device__ __forceinline__ uint32_t smem_u32(const void* p) {
    uint32_t a;
    asm("{ .reg .u64 t; cvta.to.shared.u64 t, %1; cvt.u32.u64 %0, t; }" : "=r"(a) : "l"(p));
    return a;
}
__device__ __forceinline__ void cp16(uint32_t sdst, const void* gsrc) {
    asm volatile("cp.async.cg.shared.global [%0], [%1], 16;" :: "r"(sdst), "l"(gsrc) : "memory");
}
__device__ __forceinline__ void ldm4(uint32_t* r, uint32_t a) {
    asm volatile("ldmatrix.sync.aligned.m8n8.x4.shared.b16 {%0,%1,%2,%3}, [%4];"
        : "=r"(r[0]), "=r"(r[1]), "=r"(r[2]), "=r"(r[3]) : "r"(a));
}
__device__ __forceinline__ void mma_f16(float* d, const uint32_t* a, const uint32_t* b) {
    asm volatile("mma.sync.aligned.m16n8k16.row.col.f32.f16.f16.f32 "
        "{%0,%1,%2,%3},{%4,%5,%6,%7},{%8,%9},{%0,%1,%2,%3};"
        : "+f"(d[0]), "+f"(d[1]), "+f"(d[2]), "+f"(d[3])
        : "r"(a[0]), "r"(a[1]), "r"(a[2]), "r"(a[3]), "r"(b[0]), "r"(b[1]));
}

// ================= HMMA GEMM: C[M,N] = A[M,K] @ B[N,K]^T ===============
// CTA 128x128, 8 warps (2m x 4n) of 64x32, BKC=64, 3 stages, 2 CTA/SM.
// EPI: 0 = +bias (fp32), 1 = +bias+R (fp32), 2 = gelu(+bias) -> fp16,
//      3 = +bias -> fp16
#define BM 128
#define BN 128
#define BKC 64
#define PITCHB 144                     // bytes per smem row (128B data + 16B pad)
#define TILE_SB (128 * PITCHB)         // 18432
#define STAGE_SB (2 * TILE_SB)         // 36864
#define NSTAGE 3
#define SMEM_BYTES (NSTAGE * STAGE_SB) // 110592 per CTA; x2 CTA = 216KB/SM

template<int EPI>
__global__ __launch_bounds__(256, 2) void mma_gemm(
    const __half* __restrict__ A, const __half* __restrict__ B,
    const float* __restrict__ bias, const float* __restrict__ Rres,
    float* __restrict__ Cf, __half* __restrict__ Cp,
    int M, int N, int Keff)
{
    extern __shared__ char smem[];
    const uint32_t sb = smem_u32(smem);
    const int tid = threadIdx.x;
    const int bm = blockIdx.y * BM, bn = blockIdx.x * BN;
    const int w = tid >> 5, lane = tid & 31;
    const int wm = w & 1, wn = w >> 1;       // warp grid 2(m) x 4(n), 64x32 tiles

    float acc[4][4][4];
    #pragma unroll
    for (int i = 0; i < 4; i++)
        #pragma unroll
        for (int j = 0; j < 4; j++)
            #pragma unroll
            for (int t = 0; t < 4; t++) acc[i][j][t] = 0.f;

    const int KC = Keff / BKC;

    auto load_stage = [&](int st, int c) {
        const uint32_t s0 = sb + st * STAGE_SB;
        const int k0 = c * BKC;
        #pragma unroll
        for (int i = 0; i < 4; i++) {               // A: 1024 16B chunks
            const int idx = tid + i * 256;
            const int r = idx >> 3, ch = idx & 7;
            cp16(s0 + r * PITCHB + ch * 16,
                 A + (size_t)(bm + r) * Keff + k0 + ch * 8);
        }
        #pragma unroll
        for (int i = 0; i < 4; i++) {               // B: 1024 16B chunks
            const int idx = tid + i * 256;
            const int r = idx >> 3, ch = idx & 7;
            cp16(s0 + TILE_SB + r * PITCHB + ch * 16,
                 B + (size_t)(bn + r) * Keff + k0 + ch * 8);
        }
        asm volatile("cp.async.commit_group;" ::: "memory");
    };

    load_stage(0, 0);
    load_stage(1, 1);

    for (int c = 0; c < KC; c++) {
        const int st = c % NSTAGE;
        asm volatile("cp.async.wait_group 1;" ::: "memory");
        __syncthreads();

        if (c + 2 < KC) load_stage((c + 2) % NSTAGE, c + 2);
        else asm volatile("cp.async.commit_group;" ::: "memory");

        const uint32_t sA = sb + st * STAGE_SB;
        const uint32_t sB = sA + TILE_SB;

        #pragma unroll
        for (int ks = 0; ks < 4; ks++) {
            const int kc = ks * 16;
            uint32_t afr[4][4], bfr[4][2];
            #pragma unroll
            for (int mt = 0; mt < 4; mt++) {
                const int row = wm * 64 + mt * 16 + (lane & 15);
                const int col = kc + (lane >> 4) * 8;
                ldm4(afr[mt], sA + row * PITCHB + col * 2);
            }
            #pragma unroll
            for (int np = 0; np < 2; np++) {
                const int n = wn * 32 + np * 16 + ((lane >> 4) & 1) * 8 + (lane & 7);
                const int col = kc + ((lane >> 3) & 1) * 8;
                uint32_t r[4];
                ldm4(r, sB + n * PITCHB + col * 2);
                bfr[2 * np][0] = r[0]; bfr[2 * np][1] = r[1];
                bfr[2 * np + 1][0] = r[2]; bfr[2 * np + 1][1] = r[3];
            }
            #pragma unroll
            for (int mt = 0; mt < 4; mt++)
                #pragma unroll
                for (int nt = 0; nt < 4; nt++)
                    mma_f16(acc[mt][nt], afr[mt], bfr[nt]);
        }
    }

    // -------- epilogue --------
    const int r0 = lane >> 2, cp2 = (lane & 3) * 2;
    #pragma unroll
    for (int mt = 0; mt < 4; mt++) {
        #pragma unroll
        for (int nt = 0; nt < 4; nt++) {
            const int col = bn + wn * 32 + nt * 8 + cp2;
            const float2 bv = *(const float2*)(bias + col);
            #pragma unroll
            for (int half_ = 0; half_ < 2; half_++) {
                const int row = bm + wm * 64 + mt * 16 + r0 + half_ * 8;
                float v0 = acc[mt][nt][2 * half_ + 0] + bv.x;
                float v1 = acc[mt][nt][2 * half_ + 1] + bv.y;
                if (EPI == 1) {
                    const float2 rv = *(const float2*)(Rres + (size_t)row * N + col);
                    v0 += rv.x; v1 += rv.y;
                }
                if (EPI == 2) {
                    v0 = 0.5f * v0 * (1.0f + erff(v0 * 0.70710678118654752f));
                    v1 = 0.5f * v1 * (1.0f + erff(v1 * 0.70710678118654752f));
                }
                if (EPI == 2 || EPI == 3) {
                    *(__half2*)(Cp + (size_t)row * N + col) =
                        __halves2half2(__float2half(v0), __float2half(v1));
                } else {
                    *(float2*)(Cf + (size_t)row * N + col) = make_float2(v0, v1);
                }
            }
        }
    }
}

// ---------------- fused weight prep: all transposes + bias concat ------
__global__ __launch_bounds__(256) void weight_prep(
    const float* __restrict__ wq, const float* __restrict__ wk,
    const float* __restrict__ wv, const float* __restrict__ wo,
    const float* __restrict__ fcw, const float* __restrict__ pjw,
    const float* __restrict__ bq, const float* __restrict__ bk,
    const float* __restrict__ bv,
    __half* __restrict__ wqkv, __half* __restrict__ wop,
    __half* __restrict__ fcp, __half* __restrict__ pjp,
    float* __restrict__ bqkv)
{
    const int t = blockIdx.x;
    if (t == 12288) {
        for (int i = threadIdx.x; i < DD; i += 256) {
            bqkv[i]          = bq[i];
            bqkv[DD + i]     = bk[i];
            bqkv[2 * DD + i] = bv[i];
        }
        return;
    }

    const float* W; __half* T;
    int K, N, nblk, kblk;
    if (t < 4096) {
        const int m = t >> 10, local = t & 1023;
        nblk = local & 31; kblk = local >> 5;
        K = DD; N = DD;
        W = (m == 0) ? wq : (m == 1) ? wk : (m == 2) ? wv : wo;
        T = (m == 0) ? wqkv
          : (m == 1) ? wqkv + (size_t)DD * DD
          : (m == 2) ? wqkv + (size_t)2 * DD * DD
          : wop;
    } else if (t < 8192) {
        const int local = t - 4096;
        nblk = local & 127; kblk = local >> 7;
        K = DD; N = MLP; W = fcw; T = fcp;
    } else {
        const int local = t - 8192;
        nblk = local & 31; kblk = local >> 5;
        K = MLP; N = DD; W = pjw; T = pjp;
    }

    __shared__ float tile[32][33];
    const int n0 = nblk * 32, k0 = kblk * 32;
    const int tx = threadIdx.x & 31, ty = threadIdx.x >> 5;
    #pragma unroll
    for (int i = 0; i < 32; i += 8)
        tile[ty + i][tx] = W[(size_t)(k0 + ty + i) * N + n0 + tx];
    __syncthreads();
    #pragma unroll
    for (int i = 0; i < 32; i += 8)
        T[(size_t)(n0 + ty + i) * K + k0 + tx] = __float2half(tile[tx][ty + i]);
}

// ---------------- LayerNorm -> fp16 1-seg ------------------------------
__global__ __launch_bounds__(256) void ln_f16_kernel(
    const float* __restrict__ X, const float* __restrict__ w,
    const float* __restrict__ b, __half* __restrict__ Y)
{
    const int row = blockIdx.x;
    const int tid = threadIdx.x;
    const float* x = X + (size_t)row * DD;

    float4 xv = *(const float4*)(x + tid * 4);
    float s  = xv.x + xv.y + xv.z + xv.w;
    float s2 = fmaf(xv.x, xv.x, fmaf(xv.y, xv.y, fmaf(xv.z, xv.z, xv.w * xv.w)));
    #pragma unroll
    for (int o = 16; o; o >>= 1) {
        s  += __shfl_xor_sync(0xFFFFFFFFu, s,  o);
        s2 += __shfl_xor_sync(0xFFFFFFFFu, s2, o);
    }
    __shared__ float sh[8], sh2[8];
    const int lane = tid & 31, wid = tid >> 5;
    if (lane == 0) { sh[wid] = s; sh2[wid] = s2; }
    __syncthreads();
    float S = 0.f, S2 = 0.f;
    #pragma unroll
    for (int i = 0; i < 8; i++) { S += sh[i]; S2 += sh2[i]; }
    const float mean = S * (1.0f / DD);
    const float var  = S2 * (1.0f / DD) - mean * mean;
    const float inv  = rsqrtf(var + 1e-5f);

    float4 wv = *(const float4*)(w + tid * 4);
    float4 bv = *(const float4*)(b + tid * 4);
    const size_t o = (size_t)row * DD + tid * 4;
    *(__half2*)(Y + o) = __halves2half2(
        __float2half((xv.x - mean) * inv * wv.x + bv.x),
        __float2half((xv.y - mean) * inv * wv.y + bv.y));
    *(__half2*)(Y + o + 2) = __halves2half2(
        __float2half((xv.z - mean) * inv * wv.z + bv.z),
        __float2half((xv.w - mean) * inv * wv.w + bv.w));
}

// ---------------- fused per-token linear attention (fp16 qkv) ----------
// __launch_bounds__(256,4): cap regs at 64 so 4 CTAs/SM co-reside.
__device__ __forceinline__ float elu1(float x) {
    return x > 0.f ? x + 1.0f : expf(x);
}

__global__ __launch_bounds__(256, 4) void attn_kernel(
    const __half* __restrict__ QKV, __half* __restrict__ Op)
{
    __shared__ float fq[HH][HD];
    __shared__ float fk[HH][HD];
    __shared__ float vv[HH][HD];
    __shared__ float kv[HD][HD];
    __shared__ float ksum[HD];

    const size_t base  = (size_t)blockIdx.x * D3;
    const size_t baseo = (size_t)blockIdx.x * DD;
    const int tid = threadIdx.x;

    {
        const __half2* q2 = (const __half2*)(QKV + base + tid * 4);
        const __half2* k2 = (const __half2*)(QKV + base + DD + tid * 4);
        const __half2* v2 = (const __half2*)(QKV + base + 2 * DD + tid * 4);
        const float2 qa = __half22float2(q2[0]), qb = __half22float2(q2[1]);
        const float2 ka = __half22float2(k2[0]), kb = __half22float2(k2[1]);
        const float2 va = __half22float2(v2[0]), vb = __half22float2(v2[1]);
        float* fqf = &fq[0][0]; float* fkf = &fk[0][0]; float* vvf = &vv[0][0];
        fqf[tid*4+0] = elu1(qa.x); fqf[tid*4+1] = elu1(qa.y);
        fqf[tid*4+2] = elu1(qb.x); fqf[tid*4+3] = elu1(qb.y);
        fkf[tid*4+0] = elu1(ka.x); fkf[tid*4+1] = elu1(ka.y);
        fkf[tid*4+2] = elu1(kb.x); fkf[tid*4+3] = elu1(kb.y);
        vvf[tid*4+0] = va.x; vvf[tid*4+1] = va.y;
        vvf[tid*4+2] = vb.x; vvf[tid*4+3] = vb.y;
    }
    __syncthreads();

    if (tid < HD) {
        float s = 0.f;
        #pragma unroll
        for (int h = 0; h < HH; h++) s += fk[h][tid];
        ksum[tid] = s;
    }
    {
        const int e = tid & 63;
        const int d0 = tid >> 6;
        #pragma unroll 4
        for (int j = 0; j < 16; j++) {
            const int d = d0 + j * 4;
            float s = 0.f;
            #pragma unroll
            for (int h = 0; h < HH; h++) s = fmaf(fk[h][d], vv[h][e], s);
            kv[d][e] = s;
        }
    }
    __syncthreads();
    {
        const int e = tid & 63;
        const int h0 = tid >> 6;
        #pragma unroll 1
        for (int j = 0; j < 4; j++) {
            const int h = h0 + j * 4;
            float s = 0.f, sq = 0.f;
            #pragma unroll 16
            for (int d = 0; d < HD; d++) {
                const float f = fq[h][d];
                s  = fmaf(f, kv[d][e], s);
                sq = fmaf(f, ksum[d], sq);
            }
            Op[baseo + h * HD + e] = __float2half(s / (sq + 1e-6f));
        }
    }
}

// ---------------- launch ----------------
extern "C" void kernel_launch(void* const* d_in, const int* in_sizes, int n_in,
                              void* d_out, int out_size)
{
    const float* q_x    = (const float*)d_in[0];
    const float* ln1_w  = (const float*)d_in[1];
    const float* ln1_b  = (const float*)d_in[2];
    const float* wq     = (const float*)d_in[3];
    const float* bq     = (const float*)d_in[4];
    const float* wk     = (const float*)d_in[5];
    const float* bk     = (const float*)d_in[6];
    const float* wv     = (const float*)d_in[7];
    const float* bv     = (const float*)d_in[8];
    const float* wo     = (const float*)d_in[9];
    const float* bo     = (const float*)d_in[10];
    const float* ln2_w  = (const float*)d_in[11];
    const float* ln2_b  = (const float*)d_in[12];
    const float* fc_w   = (const float*)d_in[13];
    const float* fc_b   = (const float*)d_in[14];
    const float* proj_w = (const float*)d_in[15];
    const float* proj_b = (const float*)d_in[16];
    float* out = (float*)d_out;

    __half *xnp, *ap, *hp1, *qkv, *wqkvp, *wop, *fcp, *pjp1;
    float *x, *bqkv;
    cudaGetSymbolAddress((void**)&xnp,   g_xnp);
    cudaGetSymbolAddress((void**)&ap,    g_ap);
    cudaGetSymbolAddress((void**)&hp1,   g_hp1);
    cudaGetSymbolAddress((void**)&qkv,   g_qkv);
    cudaGetSymbolAddress((void**)&x,     g_x);
    cudaGetSymbolAddress((void**)&wqkvp, g_wqkv);
    cudaGetSymbolAddress((void**)&wop,   g_wop);
    cudaGetSymbolAddress((void**)&fcp,   g_fcp);
    cudaGetSymbolAddress((void**)&pjp1,  g_pjp1);
    cudaGetSymbolAddress((void**)&bqkv,  g_bqkv);

    cudaFuncSetAttribute((const void*)mma_gemm<1>, cudaFuncAttributeMaxDynamicSharedMemorySize, SMEM_BYTES);
    cudaFuncSetAttribute((const void*)mma_gemm<2>, cudaFuncAttributeMaxDynamicSharedMemorySize, SMEM_BYTES);
    cudaFuncSetAttribute((const void*)mma_gemm<3>, cudaFuncAttributeMaxDynamicSharedMemorySize, SMEM_BYTES);

    // fused weight prep: all transposes + bias concat in one launch
    weight_prep<<<12289, 256>>>(wq, wk, wv, wo, fc_w, proj_w, bq, bk, bv,
                                wqkvp, wop, fcp, pjp1, bqkv);

    const dim3 gQKV(D3  / BN, MM / BM);  // (24, 128)
    const dim3 gD  (DD  / BN, MM / BM);  // (8, 128)
    const dim3 gML (MLP / BN, MM / BM);  // (32, 128)

    // 1) xn = LN1(q_x) -> fp16
    ln_f16_kernel<<<MM, 256>>>(q_x, ln1_w, ln1_b, xnp);
    // 2) qkv = xn @ [wq|wk|wv] + [bq|bk|bv]  (fused, fp16 out)
    mma_gemm<3><<<gQKV, 256, SMEM_BYTES>>>(xnp, wqkvp, bqkv, nullptr, nullptr, qkv, MM, D3, DD);
    // 3) fused per-token linear attention -> fp16
    attn_kernel<<<MM, 256>>>(qkv, ap);
    // 4) x = q_x + attn @ wo + bo  (fp32 out)
    mma_gemm<1><<<gD, 256, SMEM_BYTES>>>(ap, wop, bo, q_x, x, nullptr, MM, DD, DD);
    // 5) xn2 = LN2(x) -> fp16
    ln_f16_kernel<<<MM, 256>>>(x, ln2_w, ln2_b, xnp);
    // 6) h = gelu(xn2 @ fc_w + fc_b) -> fp16
    mma_gemm<2><<<gML, 256, SMEM_BYTES>>>(xnp, fcp, fc_b, nullptr, nullptr, hp1, MM, MLP, DD);
    // 7) out = x + h @ proj_w + proj_b
    mma_gemm<1><<<gD, 256, SMEM_BYTES>>>(hp1, pjp1, proj_b, x, out, nullptr, MM, DD, MLP);
}